// round 11
// baseline (speedup 1.0000x reference)
#include <cuda_runtime.h>
#include <cuda_bf16.h>
#include <cstdint>

#define BATCH   2
#define SEQ     2048
#define EMB     1024
#define HEADS   16
#define HDIM    64
#define MTOT    (BATCH*SEQ)        // 4096
#define BH      (BATCH*HEADS)      // 32
#define SCALE   0.125f

// ---------------- scratch (device globals; cudaMalloc forbidden) -----------
__device__ __nv_bfloat16 g_x_hi[MTOT*EMB],   g_x_lo[MTOT*EMB];
__device__ __nv_bfloat16 g_wq_hi[3*EMB*EMB], g_wq_lo[3*EMB*EMB];
__device__ __nv_bfloat16 g_wo_hi[EMB*EMB],   g_wo_lo[EMB*EMB];
__device__ __nv_bfloat16 g_cx_hi[MTOT*EMB],  g_cx_lo[MTOT*EMB];
__device__ __nv_bfloat16 g_q_hi[BH*SEQ*HDIM],  g_q_lo[BH*SEQ*HDIM];   // [bh][n][d], pre-scaled
__device__ __nv_bfloat16 g_k_hi[BH*SEQ*HDIM],  g_k_lo[BH*SEQ*HDIM];   // [bh][n][d]
__device__ __nv_bfloat16 g_vT_hi[BH*HDIM*SEQ], g_vT_lo[BH*HDIM*SEQ];  // [bh][d][n]

// ---------------- helpers --------------------------------------------------
__device__ __forceinline__ uint32_t smem_u32(const void* p) {
    uint32_t a;
    asm("{ .reg .u64 t; cvta.to.shared.u64 t, %1; cvt.u32.u64 %0, t; }"
        : "=r"(a) : "l"(p));
    return a;
}
#define SW(off)   ((uint32_t)(off) ^ ((((uint32_t)(off)) >> 3) & 0x70))   // SW128
#define SW64(off) ((uint32_t)(off) ^ ((((uint32_t)(off)) >> 3) & 0x30))   // SW64

__device__ __forceinline__ void ldsm_x4(uint32_t& r0, uint32_t& r1,
                                        uint32_t& r2, uint32_t& r3, uint32_t addr) {
    asm volatile("ldmatrix.sync.aligned.m8n8.x4.shared.b16 {%0,%1,%2,%3}, [%4];"
                 : "=r"(r0), "=r"(r1), "=r"(r2), "=r"(r3) : "r"(addr));
}
__device__ __forceinline__ void mma16816(float c[4],
                                         uint32_t a0, uint32_t a1, uint32_t a2, uint32_t a3,
                                         uint32_t b0, uint32_t b1) {
    asm volatile("mma.sync.aligned.m16n8k16.row.col.f32.bf16.bf16.f32 "
                 "{%0,%1,%2,%3}, {%4,%5,%6,%7}, {%8,%9}, {%0,%1,%2,%3};"
                 : "+f"(c[0]), "+f"(c[1]), "+f"(c[2]), "+f"(c[3])
                 : "r"(a0), "r"(a1), "r"(a2), "r"(a3), "r"(b0), "r"(b1));
}
__device__ __forceinline__ void cp16(uint32_t dst, const void* src) {
    asm volatile("cp.async.cg.shared.global [%0], [%1], 16;" :: "r"(dst), "l"(src));
}
#define CP_COMMIT()  asm volatile("cp.async.commit_group;" ::: "memory")
#define CP_WAIT0()   asm volatile("cp.async.wait_group 0;" ::: "memory")
#define CP_WAIT1()   asm volatile("cp.async.wait_group 1;" ::: "memory")
#define CP_WAIT2()   asm volatile("cp.async.wait_group 2;" ::: "memory")

__device__ __forceinline__ void split_pack(float v0, float v1, uint32_t& hi, uint32_t& lo) {
    __nv_bfloat16 h0 = __float2bfloat16(v0), h1 = __float2bfloat16(v1);
    __nv_bfloat16 l0 = __float2bfloat16(v0 - __bfloat162float(h0));
    __nv_bfloat16 l1 = __float2bfloat16(v1 - __bfloat162float(h1));
    hi = (uint32_t)__bfloat16_as_ushort(h0) | ((uint32_t)__bfloat16_as_ushort(h1) << 16);
    lo = (uint32_t)__bfloat16_as_ushort(l0) | ((uint32_t)__bfloat16_as_ushort(l1) << 16);
}

// ---------------------------------------------------------------------------
// Split fp32 -> bf16 hi/lo (which: 0=x, 1=w_qkv, 2=w_out)
// ---------------------------------------------------------------------------
__global__ __launch_bounds__(256) void split_kernel(
    const float* __restrict__ in, int n4, int which)
{
    int i = blockIdx.x * 256 + threadIdx.x;
    if (i >= n4) return;
    __nv_bfloat16 *hi, *lo;
    if (which == 0)      { hi = g_x_hi;  lo = g_x_lo;  }
    else if (which == 1) { hi = g_wq_hi; lo = g_wq_lo; }
    else                 { hi = g_wo_hi; lo = g_wo_lo; }
    float4 v = ((const float4*)in)[i];
    uint32_t h01, l01, h23, l23;
    split_pack(v.x, v.y, h01, l01);
    split_pack(v.z, v.w, h23, l23);
    ((uint2*)hi)[i] = make_uint2(h01, h23);
    ((uint2*)lo)[i] = make_uint2(l01, l23);
}

// ---------------------------------------------------------------------------
// HMMA split-bf16 GEMM. BK=32 (SW64, 64B rows), 3 x 32KB stages = 96KB smem,
// __launch_bounds__(256,2) => <=128 regs, 2 CTAs/SM, 16 warps/SM.
// ---------------------------------------------------------------------------
#define GSTAGE    32768
#define GEMM_SMEM (3*GSTAGE)

__global__ __launch_bounds__(256, 2) void tc_gemm(
    const float* __restrict__ bias, float* __restrict__ out, int mode)
{
    extern __shared__ char sb[];
    const uint32_t sbu = smem_u32(sb);
    const int tid = threadIdx.x;
    const int wid = tid >> 5, lane = tid & 31;
    const int wm = wid >> 2, wn = wid & 3;
    const int m0 = blockIdx.y * 128, n0 = blockIdx.x * 128;

    const char *Ahg, *Alg, *Bhg, *Blg;
    if (mode == 0) {
        Ahg = (const char*)(g_x_hi  + (size_t)m0 * EMB);
        Alg = (const char*)(g_x_lo  + (size_t)m0 * EMB);
        Bhg = (const char*)(g_wq_hi + (size_t)n0 * EMB);
        Blg = (const char*)(g_wq_lo + (size_t)n0 * EMB);
    } else {
        Ahg = (const char*)(g_cx_hi + (size_t)m0 * EMB);
        Alg = (const char*)(g_cx_lo + (size_t)m0 * EMB);
        Bhg = (const char*)(g_wo_hi + (size_t)n0 * EMB);
        Blg = (const char*)(g_wo_lo + (size_t)n0 * EMB);
    }

    float acc[4][4][4];
#pragma unroll
    for (int i = 0; i < 4; i++)
#pragma unroll
        for (int j = 0; j < 4; j++)
#pragma unroll
            for (int e = 0; e < 4; e++) acc[i][j][e] = 0.f;

    const int a_r  = (lane & 7) + ((lane >> 3) & 1) * 8;
    const int a_kb = (lane >> 4) * 16;
    const int b_r  = (lane & 7) + (lane >> 4) * 8;
    const int b_kb = ((lane >> 3) & 1) * 16;

    // stage: Ah@0 Al@8K Bh@16K Bl@24K, rows of 64B (BK=32), SW64
    auto load_stage = [&](int c, int s) {
        const uint32_t base = sbu + s * GSTAGE;
#pragma unroll
        for (int it = 0; it < 2; it++) {
            const int idx = tid + it * 256;      // 0..511
            const int r = idx >> 2, cc = (idx & 3) * 16;
            const uint32_t sw = SW64(r * 64 + cc);
            const size_t g = (size_t)r * 2048 + (size_t)c * 64 + cc;
            cp16(base + sw,          Ahg + g);
            cp16(base +  8192 + sw,  Alg + g);
            cp16(base + 16384 + sw,  Bhg + g);
            cp16(base + 24576 + sw,  Blg + g);
        }
    };

    load_stage(0, 0); CP_COMMIT();
    load_stage(1, 1); CP_COMMIT();

    for (int c = 0; c < 32; c++) {
        const int buf = c % 3;
        if (c + 2 < 32) { load_stage(c + 2, (c + 2) % 3); CP_COMMIT(); CP_WAIT2(); }
        else if (c == 30) { CP_WAIT1(); }
        else              { CP_WAIT0(); }
        __syncthreads();

        const uint32_t Ah = sbu + buf * GSTAGE;
        const uint32_t Al = Ah + 8192, Bh = Ah + 16384, Bl = Ah + 24576;
#pragma unroll
        for (int ks = 0; ks < 2; ks++) {
            const int kb = ks * 32;
            uint32_t ah[4][4], al[4][4];
#pragma unroll
            for (int mt = 0; mt < 4; mt++) {
                const int row = wm * 64 + mt * 16 + a_r;
                ldsm_x4(ah[mt][0], ah[mt][1], ah[mt][2], ah[mt][3],
                        Ah + SW64(row * 64 + kb + a_kb));
                ldsm_x4(al[mt][0], al[mt][1], al[mt][2], al[mt][3],
                        Al + SW64(row * 64 + kb + a_kb));
            }
#pragma unroll
            for (int p = 0; p < 2; p++) {
                const int row = wn * 32 + p * 16 + b_r;
                uint32_t t0, t1, t2, t3;
                ldsm_x4(t0, t1, t2, t3, Bh + SW64(row * 64 + kb + b_kb));
#pragma unroll
                for (int mt = 0; mt < 4; mt++) {
                    mma16816(acc[mt][p*2],   ah[mt][0], ah[mt][1], ah[mt][2], ah[mt][3], t0, t1);
                    mma16816(acc[mt][p*2+1], ah[mt][0], ah[mt][1], ah[mt][2], ah[mt][3], t2, t3);
                }
#pragma unroll
                for (int mt = 0; mt < 4; mt++) {
                    mma16816(acc[mt][p*2],   al[mt][0], al[mt][1], al[mt][2], al[mt][3], t0, t1);
                    mma16816(acc[mt][p*2+1], al[mt][0], al[mt][1], al[mt][2], al[mt][3], t2, t3);
                }
                ldsm_x4(t0, t1, t2, t3, Bl + SW64(row * 64 + kb + b_kb));
#pragma unroll
                for (int mt = 0; mt < 4; mt++) {
                    mma16816(acc[mt][p*2],   ah[mt][0], ah[mt][1], ah[mt][2], ah[mt][3], t0, t1);
                    mma16816(acc[mt][p*2+1], ah[mt][0], ah[mt][1], ah[mt][2], ah[mt][3], t2, t3);
                }
            }
        }
        __syncthreads();
    }

    const int rbase = m0 + wm * 64 + (lane >> 2);
    const int cbase = n0 + wn * 32 + (lane & 3) * 2;
#pragma unroll
    for (int mt = 0; mt < 4; mt++) {
#pragma unroll
        for (int nt = 0; nt < 4; nt++) {
            const int col = cbase + nt * 8;
            const float bx = bias[col], by = bias[col + 1];
#pragma unroll
            for (int half = 0; half < 2; half++) {
                const int row = rbase + mt * 16 + half * 8;
                float v0 = acc[mt][nt][half * 2 + 0] + bx;
                float v1 = acc[mt][nt][half * 2 + 1] + by;
                if (mode == 1) {
                    *(float2*)(out + (size_t)row * EMB + col) = make_float2(v0, v1);
                } else {
                    const int b = row >> 11, n = row & 2047;
                    const int which = col >> 10;
                    const int hd = col & 1023;
                    const int h = hd >> 6, d = hd & 63;
                    const int bhi = (b << 4) + h;
                    if (which == 0) {
                        uint32_t hi, lo;
                        split_pack(v0 * SCALE, v1 * SCALE, hi, lo);
                        const size_t off = ((size_t)bhi * SEQ + n) * HDIM + d;
                        *(uint32_t*)&g_q_hi[off] = hi;
                        *(uint32_t*)&g_q_lo[off] = lo;
                    } else if (which == 1) {
                        uint32_t hi, lo;
                        split_pack(v0, v1, hi, lo);
                        const size_t off = ((size_t)bhi * SEQ + n) * HDIM + d;
                        *(uint32_t*)&g_k_hi[off] = hi;
                        *(uint32_t*)&g_k_lo[off] = lo;
                    } else {
                        __nv_bfloat16 h0 = __float2bfloat16(v0);
                        __nv_bfloat16 h1 = __float2bfloat16(v1);
                        __nv_bfloat16 l0 = __float2bfloat16(v0 - __bfloat162float(h0));
                        __nv_bfloat16 l1 = __float2bfloat16(v1 - __bfloat162float(h1));
                        const size_t o0 = ((size_t)bhi * HDIM + d) * SEQ + n;
                        const size_t o1 = ((size_t)bhi * HDIM + d + 1) * SEQ + n;
                        g_vT_hi[o0] = h0; g_vT_lo[o0] = l0;
                        g_vT_hi[o1] = h1; g_vT_lo[o1] = l1;
                    }
                }
            }
        }
    }
}

// ---------------------------------------------------------------------------
// HMMA flash attention, split bf16, register-resident P.
// 512 threads (16 warps/SM), 256 q-rows/CTA, 64-key stages.
// Smem: Qh@0(32K) Ql@32K | stage s@64K+s*32K {Kh 8K, Kl 8K, VTh 8K, VTl 8K}
// 3 stages. Total 160KB.
// ---------------------------------------------------------------------------
#define ASTG      32768
#define AS_KV     65536
#define ATTN_SMEM (AS_KV + 3*ASTG)

__global__ __launch_bounds__(512, 1) void attn_kernel()
{
    extern __shared__ char sb[];
    const uint32_t sbu = smem_u32(sb);
    const int tid = threadIdx.x;
    const int wid = tid >> 5, lane = tid & 31;
    const int bh = blockIdx.x;
    const int q0 = blockIdx.y * 256;

    const int a_r  = (lane & 7) + ((lane >> 3) & 1) * 8;
    const int a_kb = (lane >> 4) * 16;
    const int b_r  = (lane & 7) + (lane >> 4) * 8;
    const int b_kb = ((lane >> 3) & 1) * 16;

    // ---- Q tile: 256 rows x 128B, hi+lo ----
    {
        const char* qh = (const char*)(g_q_hi + ((size_t)bh * SEQ + q0) * HDIM);
        const char* ql = (const char*)(g_q_lo + ((size_t)bh * SEQ + q0) * HDIM);
#pragma unroll
        for (int it = 0; it < 4; it++) {
            const int idx = tid + it * 512;      // 0..2047
            const int r = idx >> 3, cc = (idx & 7) * 16;
            const uint32_t sw = SW(r * 128 + cc);
            cp16(sbu + sw,         qh + r * 128 + cc);
            cp16(sbu + 32768 + sw, ql + r * 128 + cc);
        }
    }

    // stage for key-tile kt (64 keys): Kh/Kl 64rows x 128B; VT 64 d-rows x 128B
    auto load_stage = [&](int kt, int s) {
        const uint32_t base = sbu + AS_KV + s * ASTG;
        const char* kh = (const char*)(g_k_hi + ((size_t)bh * SEQ + kt * 64) * HDIM);
        const char* kl = (const char*)(g_k_lo + ((size_t)bh * SEQ + kt * 64) * HDIM);
        const char* vh = (const char*)(g_vT_hi + (size_t)bh * HDIM * SEQ) + (size_t)kt * 128;
        const char* vl = (const char*)(g_vT_lo + (size_t)bh * HDIM * SEQ) + (size_t)kt * 128;
        const int r = tid >> 3, cc = (tid & 7) * 16;
        const uint32_t sw = SW(r * 128 + cc);
        cp16(base + sw,          kh + r * 128 + cc);
        cp16(base +  8192 + sw,  kl + r * 128 + cc);
        cp16(base + 16384 + sw,  vh + (size_t)r * 4096 + cc);
        cp16(base + 24576 + sw,  vl + (size_t)r * 4096 + cc);
    };

    load_stage(0, 0); CP_COMMIT();
    load_stage(1, 1); CP_COMMIT();

    float o[8][4];
    float mi[2], li[2];
#pragma unroll
    for (int i = 0; i < 8; i++)
#pragma unroll
        for (int e = 0; e < 4; e++) o[i][e] = 0.f;
    mi[0] = mi[1] = -1e30f;
    li[0] = li[1] = 0.f;

    const int arow = wid * 16 + a_r;   // 0..255

    for (int kt = 0; kt < 32; kt++) {
        const int buf = kt % 3;
        if (kt + 2 < 32) { load_stage(kt + 2, (kt + 2) % 3); CP_COMMIT(); CP_WAIT2(); }
        else if (kt == 30) { CP_WAIT1(); }
        else               { CP_WAIT0(); }
        __syncthreads();

        const uint32_t Kh = sbu + AS_KV + buf * ASTG;
        const uint32_t Kl = Kh + 8192;
        const uint32_t Vh = Kh + 16384;
        const uint32_t Vl = Kh + 24576;

        // ---- S = Qh*Kh + Ql*Kh + Qh*Kl ----
        float s[8][4];
#pragma unroll
        for (int i = 0; i < 8; i++)
#pragma unroll
            for (int e = 0; e < 4; e++) s[i][e] = 0.f;

#pragma unroll
        for (int ks = 0; ks < 4; ks++) {
            const int kb = ks * 32;
            uint32_t ah0, ah1, ah2, ah3, al0, al1, al2, al3;
            ldsm_x4(ah0, ah1, ah2, ah3, sbu +         SW(arow * 128 + kb + a_kb));
            ldsm_x4(al0, al1, al2, al3, sbu + 32768 + SW(arow * 128 + kb + a_kb));
#pragma unroll
            for (int p = 0; p < 4; p++) {
                const int row = p * 16 + b_r;       // key row 0..63
                uint32_t t0, t1, t2, t3;
                ldsm_x4(t0, t1, t2, t3, Kh + SW(row * 128 + kb + b_kb));
                mma16816(s[p*2],   ah0, ah1, ah2, ah3, t0, t1);
                mma16816(s[p*2+1], ah0, ah1, ah2, ah3, t2, t3);
                mma16816(s[p*2],   al0, al1, al2, al3, t0, t1);
                mma16816(s[p*2+1], al0, al1, al2, al3, t2, t3);
                ldsm_x4(t0, t1, t2, t3, Kl + SW(row * 128 + kb + b_kb));
                mma16816(s[p*2],   ah0, ah1, ah2, ah3, t0, t1);
                mma16816(s[p*2+1], ah0, ah1, ah2, ah3, t2, t3);
            }
        }

        // ---- online softmax (rows lane>>2, lane>>2+8; quad reduce) ----
#pragma unroll
        for (int h = 0; h < 2; h++) {
            float rm = -1e30f;
#pragma unroll
            for (int nt = 0; nt < 8; nt++)
                rm = fmaxf(rm, fmaxf(s[nt][h*2], s[nt][h*2+1]));
            rm = fmaxf(rm, __shfl_xor_sync(0xffffffffu, rm, 1));
            rm = fmaxf(rm, __shfl_xor_sync(0xffffffffu, rm, 2));
            const float m2 = fmaxf(mi[h], rm);
            const float alpha = __expf(mi[h] - m2);
            float rs = 0.f;
#pragma unroll
            for (int nt = 0; nt < 8; nt++) {
                const float p0 = __expf(s[nt][h*2]   - m2);
                const float p1 = __expf(s[nt][h*2+1] - m2);
                s[nt][h*2] = p0; s[nt][h*2+1] = p1;
                rs += p0 + p1;
            }
            rs += __shfl_xor_sync(0xffffffffu, rs, 1);
            rs += __shfl_xor_sync(0xffffffffu, rs, 2);
            li[h] = li[h] * alpha + rs;
            mi[h] = m2;
#pragma unroll
            for (int nt = 0; nt < 8; nt++) {
                o[nt][h*2]   *= alpha;
                o[nt][h*2+1] *= alpha;
            }
        }

        // ---- O += Ph*Vh + Pl*Vh + Ph*Vl, register-resident P ----
#pragma unroll
        for (int kc = 0; kc < 4; kc++) {
            const int koff = kc * 32;
            uint32_t ah0, ah1, ah2, ah3, al0, al1, al2, al3;
            split_pack(s[2*kc][0],   s[2*kc][1],   ah0, al0);
            split_pack(s[2*kc][2],   s[2*kc][3],   ah1, al1);
            split_pack(s[2*kc+1][0], s[2*kc+1][1], ah2, al2);
            split_pack(s[2*kc+1][2], s[2*kc+1][3], ah3, al3);
#pragma unroll
            for (int p = 0; p < 4; p++) {
                const int row = p * 16 + b_r;       // d row 0..63
                const uint32_t va = SW(row * 128 + koff + b_kb);
                uint32_t t0, t1, t2, t3;
                ldsm_x4(t0, t1, t2, t3, Vh + va);
                mma16816(o[p*2],   ah0, ah1, ah2, ah3, t0, t1);
                mma16816(o[p*2+1], ah0, ah1, ah2, ah3, t2, t3);
                mma16816(o[p*2],   al0, al1, al2, al3, t0, t1);
                mma16816(o[p*2+1], al0, al1, al2, al3, t2, t3);
                ldsm_x4(t0, t1, t2, t3, Vl + va);
                mma16816(o[p*2],   ah0, ah1, ah2, ah3, t0, t1);
                mma16816(o[p*2+1], ah0, ah1, ah2, ah3, t2, t3);
            }
        }
        __syncthreads();
    }

    // ---- epilogue: normalize, split-bf16 ctx in [B,N,H*D] ----
    const int b = bh >> 4, h = bh & 15;
#pragma unroll
    for (int hh = 0; hh < 2; hh++) {
        const float inv = 1.f / li[hh];
        const int row = q0 + wid * 16 + (lane >> 2) + hh * 8;
        const size_t rbase = ((size_t)b * SEQ + row) * EMB + h * HDIM;
#pragma unroll
        for (int nt = 0; nt < 8; nt++) {
            const int col = (lane & 3) * 2 + nt * 8;
            uint32_t hi, lo;
            split_pack(o[nt][hh*2] * inv, o[nt][hh*2+1] * inv, hi, lo);
            *(uint32_t*)&g_cx_hi[rbase + col] = hi;
            *(uint32_t*)&g_cx_lo[rbase + col] = lo;
        }
    }
}

// ---------------------------------------------------------------------------
extern "C" void kernel_launch(void* const* d_in, const int* in_sizes, int n_in,
                              void* d_out, int out_size)
{
    const float* x     = (const float*)d_in[0];
    const float* w_qkv = (const float*)d_in[1];
    const float* b_qkv = (const float*)d_in[2];
    const float* w_out = (const float*)d_in[3];
    const float* b_out = (const float*)d_in[4];
    float* out = (float*)d_out;

    static bool attr_set = false;
    if (!attr_set) {
        cudaFuncSetAttribute(tc_gemm, cudaFuncAttributeMaxDynamicSharedMemorySize, GEMM_SMEM);
        cudaFuncSetAttribute(attn_kernel, cudaFuncAttributeMaxDynamicSharedMemorySize, ATTN_SMEM);
        attr_set = true;
    }

    split_kernel<<<(MTOT*EMB/4 + 255)/256, 256>>>(x, MTOT*EMB/4, 0);
    split_kernel<<<(3*EMB*EMB/4 + 255)/256, 256>>>(w_qkv, 3*EMB*EMB/4, 1);
    split_kernel<<<(EMB*EMB/4 + 255)/256, 256>>>(w_out, EMB*EMB/4, 2);

    tc_gemm<<<dim3(3*EMB/128, MTOT/128), 256, GEMM_SMEM>>>(b_qkv, nullptr, 0);
    attn_kernel<<<dim3(BH, SEQ/256), 512, ATTN_SMEM>>>();
    tc_gemm<<<dim3(EMB/128, MTOT/128), 256, GEMM_SMEM>>>(b_out, out, 1);
}

// round 12
// speedup vs baseline: 1.0316x; 1.0316x over previous
#include <cuda_runtime.h>
#include <cuda_bf16.h>
#include <cstdint>

#define BATCH   2
#define SEQ     2048
#define EMB     1024
#define HEADS   16
#define HDIM    64
#define MTOT    (BATCH*SEQ)        // 4096
#define BH      (BATCH*HEADS)      // 32
#define SCALE   0.125f
#define QSCALE  (0.125f * 1.4426950408889634f)   // SCALE * log2(e); scores in log2 domain

// ---------------- scratch (device globals; cudaMalloc forbidden) -----------
__device__ __nv_bfloat16 g_x_hi[MTOT*EMB],   g_x_lo[MTOT*EMB];
__device__ __nv_bfloat16 g_wq_hi[3*EMB*EMB], g_wq_lo[3*EMB*EMB];
__device__ __nv_bfloat16 g_wo_hi[EMB*EMB],   g_wo_lo[EMB*EMB];
__device__ __nv_bfloat16 g_cx_hi[MTOT*EMB],  g_cx_lo[MTOT*EMB];
__device__ __nv_bfloat16 g_q_hi[BH*SEQ*HDIM],  g_q_lo[BH*SEQ*HDIM];   // [bh][n][d], pre-scaled by QSCALE
__device__ __nv_bfloat16 g_k_hi[BH*SEQ*HDIM],  g_k_lo[BH*SEQ*HDIM];   // [bh][n][d]
__device__ __nv_bfloat16 g_vT_hi[BH*HDIM*SEQ], g_vT_lo[BH*HDIM*SEQ];  // [bh][d][n]

// ---------------- helpers --------------------------------------------------
__device__ __forceinline__ uint32_t smem_u32(const void* p) {
    uint32_t a;
    asm("{ .reg .u64 t; cvta.to.shared.u64 t, %1; cvt.u32.u64 %0, t; }"
        : "=r"(a) : "l"(p));
    return a;
}
#define SW(off)   ((uint32_t)(off) ^ ((((uint32_t)(off)) >> 3) & 0x70))   // SW128
#define SW64(off) ((uint32_t)(off) ^ ((((uint32_t)(off)) >> 3) & 0x30))   // SW64

__device__ __forceinline__ void ldsm_x4(uint32_t& r0, uint32_t& r1,
                                        uint32_t& r2, uint32_t& r3, uint32_t addr) {
    asm volatile("ldmatrix.sync.aligned.m8n8.x4.shared.b16 {%0,%1,%2,%3}, [%4];"
                 : "=r"(r0), "=r"(r1), "=r"(r2), "=r"(r3) : "r"(addr));
}
__device__ __forceinline__ void mma16816(float c[4],
                                         uint32_t a0, uint32_t a1, uint32_t a2, uint32_t a3,
                                         uint32_t b0, uint32_t b1) {
    asm volatile("mma.sync.aligned.m16n8k16.row.col.f32.bf16.bf16.f32 "
                 "{%0,%1,%2,%3}, {%4,%5,%6,%7}, {%8,%9}, {%0,%1,%2,%3};"
                 : "+f"(c[0]), "+f"(c[1]), "+f"(c[2]), "+f"(c[3])
                 : "r"(a0), "r"(a1), "r"(a2), "r"(a3), "r"(b0), "r"(b1));
}
__device__ __forceinline__ void cp16(uint32_t dst, const void* src) {
    asm volatile("cp.async.cg.shared.global [%0], [%1], 16;" :: "r"(dst), "l"(src));
}
#define CP_COMMIT()  asm volatile("cp.async.commit_group;" ::: "memory")
#define CP_WAIT0()   asm volatile("cp.async.wait_group 0;" ::: "memory")
#define CP_WAIT1()   asm volatile("cp.async.wait_group 1;" ::: "memory")
#define CP_WAIT2()   asm volatile("cp.async.wait_group 2;" ::: "memory")

__device__ __forceinline__ void split_pack(float v0, float v1, uint32_t& hi, uint32_t& lo) {
    __nv_bfloat16 h0 = __float2bfloat16(v0), h1 = __float2bfloat16(v1);
    __nv_bfloat16 l0 = __float2bfloat16(v0 - __bfloat162float(h0));
    __nv_bfloat16 l1 = __float2bfloat16(v1 - __bfloat162float(h1));
    hi = (uint32_t)__bfloat16_as_ushort(h0) | ((uint32_t)__bfloat16_as_ushort(h1) << 16);
    lo = (uint32_t)__bfloat16_as_ushort(l0) | ((uint32_t)__bfloat16_as_ushort(l1) << 16);
}

// ---------------------------------------------------------------------------
// Merged split: fp32 -> bf16 hi/lo for x, w_qkv, w_out in ONE launch
// ---------------------------------------------------------------------------
#define N4_X   (MTOT*EMB/4)
#define N4_WQ  (3*EMB*EMB/4)
#define N4_WO  (EMB*EMB/4)
#define N4_ALL (N4_X + N4_WQ + N4_WO)

__global__ __launch_bounds__(256) void split_all_kernel(
    const float* __restrict__ x, const float* __restrict__ wq,
    const float* __restrict__ wo)
{
    int i = blockIdx.x * 256 + threadIdx.x;
    if (i >= N4_ALL) return;
    const float* in;
    __nv_bfloat16 *hi, *lo;
    int j = i;
    if (j < N4_X)                { in = x;  hi = g_x_hi;  lo = g_x_lo;  }
    else if ((j -= N4_X) < N4_WQ){ in = wq; hi = g_wq_hi; lo = g_wq_lo; }
    else                         { j -= N4_WQ; in = wo; hi = g_wo_hi; lo = g_wo_lo; }
    float4 v = ((const float4*)in)[j];
    uint32_t h01, l01, h23, l23;
    split_pack(v.x, v.y, h01, l01);
    split_pack(v.z, v.w, h23, l23);
    ((uint2*)hi)[j] = make_uint2(h01, h23);
    ((uint2*)lo)[j] = make_uint2(l01, l23);
}

// ---------------------------------------------------------------------------
// HMMA split-bf16 GEMM. BK=32 (SW64), 3 x 32KB stages = 96KB smem,
// __launch_bounds__(256,2) => 2 CTAs/SM (kills GEMM2 wave-quantization tail).
// ---------------------------------------------------------------------------
#define GSTAGE    32768
#define GEMM_SMEM (3*GSTAGE)

__global__ __launch_bounds__(256, 2) void tc_gemm(
    const float* __restrict__ bias, float* __restrict__ out, int mode)
{
    extern __shared__ char sb[];
    const uint32_t sbu = smem_u32(sb);
    const int tid = threadIdx.x;
    const int wid = tid >> 5, lane = tid & 31;
    const int wm = wid >> 2, wn = wid & 3;
    const int m0 = blockIdx.y * 128, n0 = blockIdx.x * 128;

    const char *Ahg, *Alg, *Bhg, *Blg;
    if (mode == 0) {
        Ahg = (const char*)(g_x_hi  + (size_t)m0 * EMB);
        Alg = (const char*)(g_x_lo  + (size_t)m0 * EMB);
        Bhg = (const char*)(g_wq_hi + (size_t)n0 * EMB);
        Blg = (const char*)(g_wq_lo + (size_t)n0 * EMB);
    } else {
        Ahg = (const char*)(g_cx_hi + (size_t)m0 * EMB);
        Alg = (const char*)(g_cx_lo + (size_t)m0 * EMB);
        Bhg = (const char*)(g_wo_hi + (size_t)n0 * EMB);
        Blg = (const char*)(g_wo_lo + (size_t)n0 * EMB);
    }

    float acc[4][4][4];
#pragma unroll
    for (int i = 0; i < 4; i++)
#pragma unroll
        for (int j = 0; j < 4; j++)
#pragma unroll
            for (int e = 0; e < 4; e++) acc[i][j][e] = 0.f;

    const int a_r  = (lane & 7) + ((lane >> 3) & 1) * 8;
    const int a_kb = (lane >> 4) * 16;
    const int b_r  = (lane & 7) + (lane >> 4) * 8;
    const int b_kb = ((lane >> 3) & 1) * 16;

    auto load_stage = [&](int c, int s) {
        const uint32_t base = sbu + s * GSTAGE;
#pragma unroll
        for (int it = 0; it < 2; it++) {
            const int idx = tid + it * 256;
            const int r = idx >> 2, cc = (idx & 3) * 16;
            const uint32_t sw = SW64(r * 64 + cc);
            const size_t g = (size_t)r * 2048 + (size_t)c * 64 + cc;
            cp16(base + sw,          Ahg + g);
            cp16(base +  8192 + sw,  Alg + g);
            cp16(base + 16384 + sw,  Bhg + g);
            cp16(base + 24576 + sw,  Blg + g);
        }
    };

    load_stage(0, 0); CP_COMMIT();
    load_stage(1, 1); CP_COMMIT();

    for (int c = 0; c < 32; c++) {
        const int buf = c % 3;
        if (c + 2 < 32) { load_stage(c + 2, (c + 2) % 3); CP_COMMIT(); CP_WAIT2(); }
        else if (c == 30) { CP_WAIT1(); }
        else              { CP_WAIT0(); }
        __syncthreads();

        const uint32_t Ah = sbu + buf * GSTAGE;
        const uint32_t Al = Ah + 8192, Bh = Ah + 16384, Bl = Ah + 24576;
#pragma unroll
        for (int ks = 0; ks < 2; ks++) {
            const int kb = ks * 32;
            uint32_t ah[4][4], al[4][4];
#pragma unroll
            for (int mt = 0; mt < 4; mt++) {
                const int row = wm * 64 + mt * 16 + a_r;
                ldsm_x4(ah[mt][0], ah[mt][1], ah[mt][2], ah[mt][3],
                        Ah + SW64(row * 64 + kb + a_kb));
                ldsm_x4(al[mt][0], al[mt][1], al[mt][2], al[mt][3],
                        Al + SW64(row * 64 + kb + a_kb));
            }
#pragma unroll
            for (int p = 0; p < 2; p++) {
                const int row = wn * 32 + p * 16 + b_r;
                uint32_t t0, t1, t2, t3;
                ldsm_x4(t0, t1, t2, t3, Bh + SW64(row * 64 + kb + b_kb));
#pragma unroll
                for (int mt = 0; mt < 4; mt++) {
                    mma16816(acc[mt][p*2],   ah[mt][0], ah[mt][1], ah[mt][2], ah[mt][3], t0, t1);
                    mma16816(acc[mt][p*2+1], ah[mt][0], ah[mt][1], ah[mt][2], ah[mt][3], t2, t3);
                }
#pragma unroll
                for (int mt = 0; mt < 4; mt++) {
                    mma16816(acc[mt][p*2],   al[mt][0], al[mt][1], al[mt][2], al[mt][3], t0, t1);
                    mma16816(acc[mt][p*2+1], al[mt][0], al[mt][1], al[mt][2], al[mt][3], t2, t3);
                }
                ldsm_x4(t0, t1, t2, t3, Bl + SW64(row * 64 + kb + b_kb));
#pragma unroll
                for (int mt = 0; mt < 4; mt++) {
                    mma16816(acc[mt][p*2],   ah[mt][0], ah[mt][1], ah[mt][2], ah[mt][3], t0, t1);
                    mma16816(acc[mt][p*2+1], ah[mt][0], ah[mt][1], ah[mt][2], ah[mt][3], t2, t3);
                }
            }
        }
        __syncthreads();
    }

    const int rbase = m0 + wm * 64 + (lane >> 2);
    const int cbase = n0 + wn * 32 + (lane & 3) * 2;
#pragma unroll
    for (int mt = 0; mt < 4; mt++) {
#pragma unroll
        for (int nt = 0; nt < 4; nt++) {
            const int col = cbase + nt * 8;
            const float bx = bias[col], by = bias[col + 1];
#pragma unroll
            for (int half = 0; half < 2; half++) {
                const int row = rbase + mt * 16 + half * 8;
                float v0 = acc[mt][nt][half * 2 + 0] + bx;
                float v1 = acc[mt][nt][half * 2 + 1] + by;
                if (mode == 1) {
                    *(float2*)(out + (size_t)row * EMB + col) = make_float2(v0, v1);
                } else {
                    const int b = row >> 11, n = row & 2047;
                    const int which = col >> 10;
                    const int hd = col & 1023;
                    const int h = hd >> 6, d = hd & 63;
                    const int bhi = (b << 4) + h;
                    if (which == 0) {
                        uint32_t hi, lo;
                        split_pack(v0 * QSCALE, v1 * QSCALE, hi, lo);
                        const size_t off = ((size_t)bhi * SEQ + n) * HDIM + d;
                        *(uint32_t*)&g_q_hi[off] = hi;
                        *(uint32_t*)&g_q_lo[off] = lo;
                    } else if (which == 1) {
                        uint32_t hi, lo;
                        split_pack(v0, v1, hi, lo);
                        const size_t off = ((size_t)bhi * SEQ + n) * HDIM + d;
                        *(uint32_t*)&g_k_hi[off] = hi;
                        *(uint32_t*)&g_k_lo[off] = lo;
                    } else {
                        __nv_bfloat16 h0 = __float2bfloat16(v0);
                        __nv_bfloat16 h1 = __float2bfloat16(v1);
                        __nv_bfloat16 l0 = __float2bfloat16(v0 - __bfloat162float(h0));
                        __nv_bfloat16 l1 = __float2bfloat16(v1 - __bfloat162float(h1));
                        const size_t o0 = ((size_t)bhi * HDIM + d) * SEQ + n;
                        const size_t o1 = ((size_t)bhi * HDIM + d + 1) * SEQ + n;
                        g_vT_hi[o0] = h0; g_vT_lo[o0] = l0;
                        g_vT_hi[o1] = h1; g_vT_lo[o1] = l1;
                    }
                }
            }
        }
    }
}

// ---------------------------------------------------------------------------
// HMMA flash attention (R9 best config): 128q/256thr, register-resident P,
// 3-stage KV pipeline. Scores are in log2 domain (QSCALE), softmax via exp2f.
// Smem: Qh@0 Ql@16K | stage s@32K+s*64K {Kh,Kl,VTh(2x8K),VTl(2x8K)}. 224KB.
// ---------------------------------------------------------------------------
#define ASTG      65536
#define AS_KV     32768
#define ATTN_SMEM (AS_KV + 3*ASTG)

__global__ __launch_bounds__(256) void attn_kernel()
{
    extern __shared__ char sb[];
    const uint32_t sbu = smem_u32(sb);
    const int tid = threadIdx.x;
    const int wid = tid >> 5, lane = tid & 31;
    const int bh = blockIdx.x;
    const int q0 = blockIdx.y * 128;

    const int a_r  = (lane & 7) + ((lane >> 3) & 1) * 8;
    const int a_kb = (lane >> 4) * 16;
    const int b_r  = (lane & 7) + (lane >> 4) * 8;
    const int b_kb = ((lane >> 3) & 1) * 16;

    // ---- Q tile ----
    {
        const char* qh = (const char*)(g_q_hi + ((size_t)bh * SEQ + q0) * HDIM);
        const char* ql = (const char*)(g_q_lo + ((size_t)bh * SEQ + q0) * HDIM);
#pragma unroll
        for (int it = 0; it < 4; it++) {
            const int idx = tid + it * 256;
            const int r = idx >> 3, in = (idx & 7) * 16;
            const uint32_t sw = SW(r * 128 + in);
            cp16(sbu + sw,         qh + r * 128 + in);
            cp16(sbu + 16384 + sw, ql + r * 128 + in);
        }
    }

    auto load_stage = [&](int kt, int s) {
        const uint32_t base = sbu + AS_KV + s * ASTG;
        const char* kh = (const char*)(g_k_hi + ((size_t)bh * SEQ + kt * 128) * HDIM);
        const char* kl = (const char*)(g_k_lo + ((size_t)bh * SEQ + kt * 128) * HDIM);
#pragma unroll
        for (int it = 0; it < 4; it++) {
            const int idx = tid + it * 256;
            const int r = idx >> 3, in = (idx & 7) * 16;
            const uint32_t sw = SW(r * 128 + in);
            cp16(base + sw,         kh + r * 128 + in);
            cp16(base + 16384 + sw, kl + r * 128 + in);
        }
        const char* vh = (const char*)(g_vT_hi + (size_t)bh * HDIM * SEQ) + (size_t)kt * 256;
        const char* vl = (const char*)(g_vT_lo + (size_t)bh * HDIM * SEQ) + (size_t)kt * 256;
#pragma unroll
        for (int it = 0; it < 4; it++) {
            const int idx = tid + it * 256;
            const int r = idx >> 4;
            const int inner = (idx & 15) * 16;
            const int half = inner >> 7, in128 = inner & 127;
            const uint32_t dst = base + 32768 + half * 8192 + SW(r * 128 + in128);
            cp16(dst,         vh + (size_t)r * 4096 + inner);
            cp16(dst + 16384, vl + (size_t)r * 4096 + inner);
        }
    };

    load_stage(0, 0); CP_COMMIT();
    load_stage(1, 1); CP_COMMIT();

    float o[8][4];
    float mi[2], li[2];
#pragma unroll
    for (int i = 0; i < 8; i++)
#pragma unroll
        for (int e = 0; e < 4; e++) o[i][e] = 0.f;
    mi[0] = mi[1] = -1e30f;
    li[0] = li[1] = 0.f;

    const int arow = wid * 16 + a_r;

    for (int kt = 0; kt < 16; kt++) {
        const int buf = kt % 3;
        if (kt + 2 < 16) { load_stage(kt + 2, (kt + 2) % 3); CP_COMMIT(); CP_WAIT2(); }
        else if (kt == 14) { CP_WAIT1(); }
        else               { CP_WAIT0(); }
        __syncthreads();

        const uint32_t Kh = sbu + AS_KV + buf * ASTG;
        const uint32_t Kl = Kh + 16384;
        const uint32_t Vh = Kh + 32768;
        const uint32_t Vl = Kh + 49152;

        // ---- S = Qh*Kh + Ql*Kh + Qh*Kl ----
        float s[16][4];
#pragma unroll
        for (int i = 0; i < 16; i++)
#pragma unroll
            for (int e = 0; e < 4; e++) s[i][e] = 0.f;

#pragma unroll
        for (int ks = 0; ks < 4; ks++) {
            const int kb = ks * 32;
            uint32_t ah0, ah1, ah2, ah3, al0, al1, al2, al3;
            ldsm_x4(ah0, ah1, ah2, ah3, sbu +         SW(arow * 128 + kb + a_kb));
            ldsm_x4(al0, al1, al2, al3, sbu + 16384 + SW(arow * 128 + kb + a_kb));
#pragma unroll
            for (int p = 0; p < 8; p++) {
                const int row = p * 16 + b_r;
                uint32_t t0, t1, t2, t3;
                ldsm_x4(t0, t1, t2, t3, Kh + SW(row * 128 + kb + b_kb));
                mma16816(s[p*2],   ah0, ah1, ah2, ah3, t0, t1);
                mma16816(s[p*2+1], ah0, ah1, ah2, ah3, t2, t3);
                mma16816(s[p*2],   al0, al1, al2, al3, t0, t1);
                mma16816(s[p*2+1], al0, al1, al2, al3, t2, t3);
                ldsm_x4(t0, t1, t2, t3, Kl + SW(row * 128 + kb + b_kb));
                mma16816(s[p*2],   ah0, ah1, ah2, ah3, t0, t1);
                mma16816(s[p*2+1], ah0, ah1, ah2, ah3, t2, t3);
            }
        }

        // ---- online softmax in log2 domain (exp2f) ----
#pragma unroll
        for (int h = 0; h < 2; h++) {
            float rm = -1e30f;
#pragma unroll
            for (int nt = 0; nt < 16; nt++)
                rm = fmaxf(rm, fmaxf(s[nt][h*2], s[nt][h*2+1]));
            rm = fmaxf(rm, __shfl_xor_sync(0xffffffffu, rm, 1));
            rm = fmaxf(rm, __shfl_xor_sync(0xffffffffu, rm, 2));
            const float m2 = fmaxf(mi[h], rm);
            const float alpha = exp2f(mi[h] - m2);
            float rs = 0.f;
#pragma unroll
            for (int nt = 0; nt < 16; nt++) {
                const float p0 = exp2f(s[nt][h*2]   - m2);
                const float p1 = exp2f(s[nt][h*2+1] - m2);
                s[nt][h*2] = p0; s[nt][h*2+1] = p1;
                rs += p0 + p1;
            }
            rs += __shfl_xor_sync(0xffffffffu, rs, 1);
            rs += __shfl_xor_sync(0xffffffffu, rs, 2);
            li[h] = li[h] * alpha + rs;
            mi[h] = m2;
#pragma unroll
            for (int nt = 0; nt < 8; nt++) {
                o[nt][h*2]   *= alpha;
                o[nt][h*2+1] *= alpha;
            }
        }

        // ---- O += Ph*Vh + Pl*Vh + Ph*Vl, P fed straight from registers ----
#pragma unroll
        for (int kc = 0; kc < 8; kc++) {
            const int half = kc >> 2;
            const int koff = (kc & 3) * 32;
            uint32_t ah0, ah1, ah2, ah3, al0, al1, al2, al3;
            split_pack(s[2*kc][0],   s[2*kc][1],   ah0, al0);
            split_pack(s[2*kc][2],   s[2*kc][3],   ah1, al1);
            split_pack(s[2*kc+1][0], s[2*kc+1][1], ah2, al2);
            split_pack(s[2*kc+1][2], s[2*kc+1][3], ah3, al3);
#pragma unroll
            for (int p = 0; p < 4; p++) {
                const int row = p * 16 + b_r;
                uint32_t t0, t1, t2, t3;
                const uint32_t va = half * 8192 + SW(row * 128 + koff + b_kb);
                ldsm_x4(t0, t1, t2, t3, Vh + va);
                mma16816(o[p*2],   ah0, ah1, ah2, ah3, t0, t1);
                mma16816(o[p*2+1], ah0, ah1, ah2, ah3, t2, t3);
                mma16816(o[p*2],   al0, al1, al2, al3, t0, t1);
                mma16816(o[p*2+1], al0, al1, al2, al3, t2, t3);
                ldsm_x4(t0, t1, t2, t3, Vl + va);
                mma16816(o[p*2],   ah0, ah1, ah2, ah3, t0, t1);
                mma16816(o[p*2+1], ah0, ah1, ah2, ah3, t2, t3);
            }
        }
        __syncthreads();
    }

    // ---- epilogue: normalize, split-bf16 ctx in [B,N,H*D] ----
    const int b = bh >> 4, h = bh & 15;
#pragma unroll
    for (int hh = 0; hh < 2; hh++) {
        const float inv = 1.f / li[hh];
        const int row = q0 + wid * 16 + (lane >> 2) + hh * 8;
        const size_t rbase = ((size_t)b * SEQ + row) * EMB + h * HDIM;
#pragma unroll
        for (int nt = 0; nt < 8; nt++) {
            const int col = (lane & 3) * 2 + nt * 8;
            uint32_t hi, lo;
            split_pack(o[nt][hh*2] * inv, o[nt][hh*2+1] * inv, hi, lo);
            *(uint32_t*)&g_cx_hi[rbase + col] = hi;
            *(uint32_t*)&g_cx_lo[rbase + col] = lo;
        }
    }
}

// ---------------------------------------------------------------------------
extern "C" void kernel_launch(void* const* d_in, const int* in_sizes, int n_in,
                              void* d_out, int out_size)
{
    const float* x     = (const float*)d_in[0];
    const float* w_qkv = (const float*)d_in[1];
    const float* b_qkv = (const float*)d_in[2];
    const float* w_out = (const float*)d_in[3];
    const float* b_out = (const float*)d_in[4];
    float* out = (float*)d_out;

    static bool attr_set = false;
    if (!attr_set) {
        cudaFuncSetAttribute(tc_gemm, cudaFuncAttributeMaxDynamicSharedMemorySize, GEMM_SMEM);
        cudaFuncSetAttribute(attn_kernel, cudaFuncAttributeMaxDynamicSharedMemorySize, ATTN_SMEM);
        attr_set = true;
    }

    split_all_kernel<<<(N4_ALL + 255)/256, 256>>>(x, w_qkv, w_out);
    tc_gemm<<<dim3(3*EMB/128, MTOT/128), 256, GEMM_SMEM>>>(b_qkv, nullptr, 0);
    attn_kernel<<<dim3(BH, SEQ/128), 256, ATTN_SMEM>>>();
    tc_gemm<<<dim3(EMB/128, MTOT/128), 256, GEMM_SMEM>>>(b_out, out, 1);
}

// round 13
// speedup vs baseline: 1.4121x; 1.3688x over previous
#include <cuda_runtime.h>
#include <cuda_fp16.h>
#include <cstdint>

#define BATCH   2
#define SEQ     2048
#define EMB     1024
#define HEADS   16
#define HDIM    64
#define MTOT    (BATCH*SEQ)        // 4096
#define BH      (BATCH*HEADS)      // 32
#define QSCALE  (0.125f * 1.4426950408889634f)   // SCALE * log2(e)

// ---------------- scratch (device globals; cudaMalloc forbidden) -----------
__device__ __half g_x_hi[MTOT*EMB],  g_x_lo[MTOT*EMB];
__device__ __half g_wq_hi[3*EMB*EMB];
__device__ __half g_wo_hi[EMB*EMB];
__device__ __half g_cx_hi[MTOT*EMB], g_cx_lo[MTOT*EMB];
__device__ __half g_q_hi[BH*SEQ*HDIM], g_q_lo[BH*SEQ*HDIM];  // [bh][n][d], pre-scaled
__device__ __half g_k_hi[BH*SEQ*HDIM];                        // [bh][n][d]
__device__ __half g_vT_hi[BH*HDIM*SEQ];                       // [bh][d][n]

// ---------------- helpers --------------------------------------------------
__device__ __forceinline__ uint32_t smem_u32(const void* p) {
    uint32_t a;
    asm("{ .reg .u64 t; cvta.to.shared.u64 t, %1; cvt.u32.u64 %0, t; }"
        : "=r"(a) : "l"(p));
    return a;
}
#define SW(off)   ((uint32_t)(off) ^ ((((uint32_t)(off)) >> 3) & 0x70))   // SW128
#define SW64(off) ((uint32_t)(off) ^ ((((uint32_t)(off)) >> 3) & 0x30))   // SW64

__device__ __forceinline__ void ldsm_x4(uint32_t& r0, uint32_t& r1,
                                        uint32_t& r2, uint32_t& r3, uint32_t addr) {
    asm volatile("ldmatrix.sync.aligned.m8n8.x4.shared.b16 {%0,%1,%2,%3}, [%4];"
                 : "=r"(r0), "=r"(r1), "=r"(r2), "=r"(r3) : "r"(addr));
}
__device__ __forceinline__ void mma16816(float c[4],
                                         uint32_t a0, uint32_t a1, uint32_t a2, uint32_t a3,
                                         uint32_t b0, uint32_t b1) {
    asm volatile("mma.sync.aligned.m16n8k16.row.col.f32.f16.f16.f32 "
                 "{%0,%1,%2,%3}, {%4,%5,%6,%7}, {%8,%9}, {%0,%1,%2,%3};"
                 : "+f"(c[0]), "+f"(c[1]), "+f"(c[2]), "+f"(c[3])
                 : "r"(a0), "r"(a1), "r"(a2), "r"(a3), "r"(b0), "r"(b1));
}
__device__ __forceinline__ void cp16(uint32_t dst, const void* src) {
    asm volatile("cp.async.cg.shared.global [%0], [%1], 16;" :: "r"(dst), "l"(src));
}
#define CP_COMMIT()  asm volatile("cp.async.commit_group;" ::: "memory")
#define CP_WAIT0()   asm volatile("cp.async.wait_group 0;" ::: "memory")
#define CP_WAIT1()   asm volatile("cp.async.wait_group 1;" ::: "memory")
#define CP_WAIT2()   asm volatile("cp.async.wait_group 2;" ::: "memory")

// fp16 split: x = hi + lo (hi/lo fp16), packs two values per uint32
__device__ __forceinline__ void split_pack_h(float v0, float v1, uint32_t& hi, uint32_t& lo) {
    __half h0 = __float2half_rn(v0), h1 = __float2half_rn(v1);
    __half l0 = __float2half_rn(v0 - __half2float(h0));
    __half l1 = __float2half_rn(v1 - __half2float(h1));
    hi = (uint32_t)__half_as_ushort(h0) | ((uint32_t)__half_as_ushort(h1) << 16);
    lo = (uint32_t)__half_as_ushort(l0) | ((uint32_t)__half_as_ushort(l1) << 16);
}
__device__ __forceinline__ uint32_t pack_h(float v0, float v1) {
    return (uint32_t)__half_as_ushort(__float2half_rn(v0)) |
           ((uint32_t)__half_as_ushort(__float2half_rn(v1)) << 16);
}

// ---------------------------------------------------------------------------
// Merged split: x -> fp16 hi+lo;  w_qkv, w_out -> fp16 hi only
// ---------------------------------------------------------------------------
#define N4_X   (MTOT*EMB/4)
#define N4_WQ  (3*EMB*EMB/4)
#define N4_WO  (EMB*EMB/4)
#define N4_ALL (N4_X + N4_WQ + N4_WO)

__global__ __launch_bounds__(256) void split_all_kernel(
    const float* __restrict__ x, const float* __restrict__ wq,
    const float* __restrict__ wo)
{
    int i = blockIdx.x * 256 + threadIdx.x;
    if (i >= N4_ALL) return;
    int j = i;
    if (j < N4_X) {
        float4 v = ((const float4*)x)[j];
        uint32_t h01, l01, h23, l23;
        split_pack_h(v.x, v.y, h01, l01);
        split_pack_h(v.z, v.w, h23, l23);
        ((uint2*)g_x_hi)[j] = make_uint2(h01, h23);
        ((uint2*)g_x_lo)[j] = make_uint2(l01, l23);
    } else if ((j -= N4_X) < N4_WQ) {
        float4 v = ((const float4*)wq)[j];
        ((uint2*)g_wq_hi)[j] = make_uint2(pack_h(v.x, v.y), pack_h(v.z, v.w));
    } else {
        j -= N4_WQ;
        float4 v = ((const float4*)wo)[j];
        ((uint2*)g_wo_hi)[j] = make_uint2(pack_h(v.x, v.y), pack_h(v.z, v.w));
    }
}

// ---------------------------------------------------------------------------
// HMMA fp16 one-sided-split GEMM: D = (Ah+Al)[M,K] * Bh[N,K]^T + bias.
// BK=32 (SW64). Stage 24KB {Ah@0, Al@8K, Bh@16K} x3 = 72KB. 2 CTAs/SM.
// mode 0: scatter Q(scaled,hi+lo)/K(hi)/V^T(hi);  mode 1: fp32 out.
// ---------------------------------------------------------------------------
#define GSTAGE    24576
#define GEMM_SMEM (3*GSTAGE)

__global__ __launch_bounds__(256, 2) void tc_gemm(
    const float* __restrict__ bias, float* __restrict__ out, int mode)
{
    extern __shared__ char sb[];
    const uint32_t sbu = smem_u32(sb);
    const int tid = threadIdx.x;
    const int wid = tid >> 5, lane = tid & 31;
    const int wm = wid >> 2, wn = wid & 3;
    const int m0 = blockIdx.y * 128, n0 = blockIdx.x * 128;

    const char *Ahg, *Alg, *Bhg;
    if (mode == 0) {
        Ahg = (const char*)(g_x_hi  + (size_t)m0 * EMB);
        Alg = (const char*)(g_x_lo  + (size_t)m0 * EMB);
        Bhg = (const char*)(g_wq_hi + (size_t)n0 * EMB);
    } else {
        Ahg = (const char*)(g_cx_hi + (size_t)m0 * EMB);
        Alg = (const char*)(g_cx_lo + (size_t)m0 * EMB);
        Bhg = (const char*)(g_wo_hi + (size_t)n0 * EMB);
    }

    float acc[4][4][4];
#pragma unroll
    for (int i = 0; i < 4; i++)
#pragma unroll
        for (int j = 0; j < 4; j++)
#pragma unroll
            for (int e = 0; e < 4; e++) acc[i][j][e] = 0.f;

    const int a_r  = (lane & 7) + ((lane >> 3) & 1) * 8;
    const int a_kb = (lane >> 4) * 16;
    const int b_r  = (lane & 7) + (lane >> 4) * 8;
    const int b_kb = ((lane >> 3) & 1) * 16;

    auto load_stage = [&](int c, int s) {
        const uint32_t base = sbu + s * GSTAGE;
#pragma unroll
        for (int it = 0; it < 2; it++) {
            const int idx = tid + it * 256;
            const int r = idx >> 2, cc = (idx & 3) * 16;
            const uint32_t sw = SW64(r * 64 + cc);
            const size_t g = (size_t)r * 2048 + (size_t)c * 64 + cc;
            cp16(base + sw,          Ahg + g);
            cp16(base +  8192 + sw,  Alg + g);
            cp16(base + 16384 + sw,  Bhg + g);
        }
    };

    load_stage(0, 0); CP_COMMIT();
    load_stage(1, 1); CP_COMMIT();

    for (int c = 0; c < 32; c++) {
        const int buf = c % 3;
        if (c + 2 < 32) { load_stage(c + 2, (c + 2) % 3); CP_COMMIT(); CP_WAIT2(); }
        else if (c == 30) { CP_WAIT1(); }
        else              { CP_WAIT0(); }
        __syncthreads();

        const uint32_t Ah = sbu + buf * GSTAGE;
        const uint32_t Al = Ah + 8192, Bh = Ah + 16384;
#pragma unroll
        for (int ks = 0; ks < 2; ks++) {
            const int kb = ks * 32;
            uint32_t ah[4][4], al[4][4], bh[2][4];
#pragma unroll
            for (int mt = 0; mt < 4; mt++) {
                const int row = wm * 64 + mt * 16 + a_r;
                ldsm_x4(ah[mt][0], ah[mt][1], ah[mt][2], ah[mt][3],
                        Ah + SW64(row * 64 + kb + a_kb));
                ldsm_x4(al[mt][0], al[mt][1], al[mt][2], al[mt][3],
                        Al + SW64(row * 64 + kb + a_kb));
            }
#pragma unroll
            for (int p = 0; p < 2; p++) {
                const int row = wn * 32 + p * 16 + b_r;
                ldsm_x4(bh[p][0], bh[p][1], bh[p][2], bh[p][3],
                        Bh + SW64(row * 64 + kb + b_kb));
            }
            // pass 1: Ah x Bh
#pragma unroll
            for (int mt = 0; mt < 4; mt++)
#pragma unroll
                for (int p = 0; p < 2; p++) {
                    mma16816(acc[mt][p*2],   ah[mt][0], ah[mt][1], ah[mt][2], ah[mt][3], bh[p][0], bh[p][1]);
                    mma16816(acc[mt][p*2+1], ah[mt][0], ah[mt][1], ah[mt][2], ah[mt][3], bh[p][2], bh[p][3]);
                }
            // pass 2: Al x Bh
#pragma unroll
            for (int mt = 0; mt < 4; mt++)
#pragma unroll
                for (int p = 0; p < 2; p++) {
                    mma16816(acc[mt][p*2],   al[mt][0], al[mt][1], al[mt][2], al[mt][3], bh[p][0], bh[p][1]);
                    mma16816(acc[mt][p*2+1], al[mt][0], al[mt][1], al[mt][2], al[mt][3], bh[p][2], bh[p][3]);
                }
        }
        __syncthreads();
    }

    const int rbase = m0 + wm * 64 + (lane >> 2);
    const int cbase = n0 + wn * 32 + (lane & 3) * 2;
#pragma unroll
    for (int mt = 0; mt < 4; mt++) {
#pragma unroll
        for (int nt = 0; nt < 4; nt++) {
            const int col = cbase + nt * 8;
            const float bx = bias[col], by = bias[col + 1];
#pragma unroll
            for (int half = 0; half < 2; half++) {
                const int row = rbase + mt * 16 + half * 8;
                float v0 = acc[mt][nt][half * 2 + 0] + bx;
                float v1 = acc[mt][nt][half * 2 + 1] + by;
                if (mode == 1) {
                    *(float2*)(out + (size_t)row * EMB + col) = make_float2(v0, v1);
                } else {
                    const int b = row >> 11, n = row & 2047;
                    const int which = col >> 10;
                    const int hd = col & 1023;
                    const int h = hd >> 6, d = hd & 63;
                    const int bhi = (b << 4) + h;
                    if (which == 0) {
                        uint32_t hi, lo;
                        split_pack_h(v0 * QSCALE, v1 * QSCALE, hi, lo);
                        const size_t off = ((size_t)bhi * SEQ + n) * HDIM + d;
                        *(uint32_t*)&g_q_hi[off] = hi;
                        *(uint32_t*)&g_q_lo[off] = lo;
                    } else if (which == 1) {
                        const size_t off = ((size_t)bhi * SEQ + n) * HDIM + d;
                        *(uint32_t*)&g_k_hi[off] = pack_h(v0, v1);
                    } else {
                        const size_t o0 = ((size_t)bhi * HDIM + d) * SEQ + n;
                        const size_t o1 = ((size_t)bhi * HDIM + d + 1) * SEQ + n;
                        g_vT_hi[o0] = __float2half_rn(v0);
                        g_vT_hi[o1] = __float2half_rn(v1);
                    }
                }
            }
        }
    }
}

// ---------------------------------------------------------------------------
// HMMA flash attention, fp16 one-sided split, register-resident P.
// S = Qh*Kh + Ql*Kh;  O += Ph*Vh + Pl*Vh.  Scores in log2 domain (exp2f).
// Smem: Qh@0 Ql@16K | stage s@32K+s*32K {Kh 16K, VTh 2x8K}. 3 stages. 128KB.
// ---------------------------------------------------------------------------
#define ASTG      32768
#define AS_KV     32768
#define ATTN_SMEM (AS_KV + 3*ASTG)

__global__ __launch_bounds__(256) void attn_kernel()
{
    extern __shared__ char sb[];
    const uint32_t sbu = smem_u32(sb);
    const int tid = threadIdx.x;
    const int wid = tid >> 5, lane = tid & 31;
    const int bh = blockIdx.x;
    const int q0 = blockIdx.y * 128;

    const int a_r  = (lane & 7) + ((lane >> 3) & 1) * 8;
    const int a_kb = (lane >> 4) * 16;
    const int b_r  = (lane & 7) + (lane >> 4) * 8;
    const int b_kb = ((lane >> 3) & 1) * 16;

    // ---- Q tile (hi+lo) ----
    {
        const char* qh = (const char*)(g_q_hi + ((size_t)bh * SEQ + q0) * HDIM);
        const char* ql = (const char*)(g_q_lo + ((size_t)bh * SEQ + q0) * HDIM);
#pragma unroll
        for (int it = 0; it < 4; it++) {
            const int idx = tid + it * 256;
            const int r = idx >> 3, in = (idx & 7) * 16;
            const uint32_t sw = SW(r * 128 + in);
            cp16(sbu + sw,         qh + r * 128 + in);
            cp16(sbu + 16384 + sw, ql + r * 128 + in);
        }
    }

    auto load_stage = [&](int kt, int s) {
        const uint32_t base = sbu + AS_KV + s * ASTG;
        const char* kh = (const char*)(g_k_hi + ((size_t)bh * SEQ + kt * 128) * HDIM);
#pragma unroll
        for (int it = 0; it < 4; it++) {
            const int idx = tid + it * 256;
            const int r = idx >> 3, in = (idx & 7) * 16;
            cp16(base + SW(r * 128 + in), kh + r * 128 + in);
        }
        const char* vh = (const char*)(g_vT_hi + (size_t)bh * HDIM * SEQ) + (size_t)kt * 256;
#pragma unroll
        for (int it = 0; it < 4; it++) {
            const int idx = tid + it * 256;
            const int r = idx >> 4;               // d row 0..63
            const int inner = (idx & 15) * 16;    // byte in 256B row
            const int half = inner >> 7, in128 = inner & 127;
            cp16(base + 16384 + half * 8192 + SW(r * 128 + in128),
                 vh + (size_t)r * 4096 + inner);
        }
    };

    load_stage(0, 0); CP_COMMIT();
    load_stage(1, 1); CP_COMMIT();

    float o[8][4];
    float mi[2], li[2];
#pragma unroll
    for (int i = 0; i < 8; i++)
#pragma unroll
        for (int e = 0; e < 4; e++) o[i][e] = 0.f;
    mi[0] = mi[1] = -1e30f;
    li[0] = li[1] = 0.f;

    const int arow = wid * 16 + a_r;

    for (int kt = 0; kt < 16; kt++) {
        const int buf = kt % 3;
        if (kt + 2 < 16) { load_stage(kt + 2, (kt + 2) % 3); CP_COMMIT(); CP_WAIT2(); }
        else if (kt == 14) { CP_WAIT1(); }
        else               { CP_WAIT0(); }
        __syncthreads();

        const uint32_t Kh = sbu + AS_KV + buf * ASTG;
        const uint32_t Vh = Kh + 16384;

        // ---- S = Qh*Kh + Ql*Kh ----
        float s[16][4];
#pragma unroll
        for (int i = 0; i < 16; i++)
#pragma unroll
            for (int e = 0; e < 4; e++) s[i][e] = 0.f;

#pragma unroll
        for (int ks = 0; ks < 4; ks++) {
            const int kb = ks * 32;
            uint32_t ah0, ah1, ah2, ah3, al0, al1, al2, al3;
            ldsm_x4(ah0, ah1, ah2, ah3, sbu +         SW(arow * 128 + kb + a_kb));
            ldsm_x4(al0, al1, al2, al3, sbu + 16384 + SW(arow * 128 + kb + a_kb));
#pragma unroll
            for (int p = 0; p < 8; p++) {
                const int row = p * 16 + b_r;
                uint32_t t0, t1, t2, t3;
                ldsm_x4(t0, t1, t2, t3, Kh + SW(row * 128 + kb + b_kb));
                mma16816(s[p*2],   ah0, ah1, ah2, ah3, t0, t1);
                mma16816(s[p*2+1], ah0, ah1, ah2, ah3, t2, t3);
                mma16816(s[p*2],   al0, al1, al2, al3, t0, t1);
                mma16816(s[p*2+1], al0, al1, al2, al3, t2, t3);
            }
        }

        // ---- online softmax in log2 domain ----
#pragma unroll
        for (int h = 0; h < 2; h++) {
            float rm = -1e30f;
#pragma unroll
            for (int nt = 0; nt < 16; nt++)
                rm = fmaxf(rm, fmaxf(s[nt][h*2], s[nt][h*2+1]));
            rm = fmaxf(rm, __shfl_xor_sync(0xffffffffu, rm, 1));
            rm = fmaxf(rm, __shfl_xor_sync(0xffffffffu, rm, 2));
            const float m2 = fmaxf(mi[h], rm);
            const float alpha = exp2f(mi[h] - m2);
            float rs = 0.f;
#pragma unroll
            for (int nt = 0; nt < 16; nt++) {
                const float p0 = exp2f(s[nt][h*2]   - m2);
                const float p1 = exp2f(s[nt][h*2+1] - m2);
                s[nt][h*2] = p0; s[nt][h*2+1] = p1;
                rs += p0 + p1;
            }
            rs += __shfl_xor_sync(0xffffffffu, rs, 1);
            rs += __shfl_xor_sync(0xffffffffu, rs, 2);
            li[h] = li[h] * alpha + rs;
            mi[h] = m2;
#pragma unroll
            for (int nt = 0; nt < 8; nt++) {
                o[nt][h*2]   *= alpha;
                o[nt][h*2+1] *= alpha;
            }
        }

        // ---- O += Ph*Vh + Pl*Vh, P from registers (fp16 hi+lo) ----
#pragma unroll
        for (int kc = 0; kc < 8; kc++) {
            const int half = kc >> 2;
            const int koff = (kc & 3) * 32;
            uint32_t ah0, ah1, ah2, ah3, al0, al1, al2, al3;
            split_pack_h(s[2*kc][0],   s[2*kc][1],   ah0, al0);
            split_pack_h(s[2*kc][2],   s[2*kc][3],   ah1, al1);
            split_pack_h(s[2*kc+1][0], s[2*kc+1][1], ah2, al2);
            split_pack_h(s[2*kc+1][2], s[2*kc+1][3], ah3, al3);
#pragma unroll
            for (int p = 0; p < 4; p++) {
                const int row = p * 16 + b_r;
                uint32_t t0, t1, t2, t3;
                ldsm_x4(t0, t1, t2, t3, Vh + half * 8192 + SW(row * 128 + koff + b_kb));
                mma16816(o[p*2],   ah0, ah1, ah2, ah3, t0, t1);
                mma16816(o[p*2+1], ah0, ah1, ah2, ah3, t2, t3);
                mma16816(o[p*2],   al0, al1, al2, al3, t0, t1);
                mma16816(o[p*2+1], al0, al1, al2, al3, t2, t3);
            }
        }
        __syncthreads();
    }

    // ---- epilogue: normalize, fp16 hi/lo ctx in [B,N,H*D] ----
    const int b = bh >> 4, h = bh & 15;
#pragma unroll
    for (int hh = 0; hh < 2; hh++) {
        const float inv = 1.f / li[hh];
        const int row = q0 + wid * 16 + (lane >> 2) + hh * 8;
        const size_t rbase = ((size_t)b * SEQ + row) * EMB + h * HDIM;
#pragma unroll
        for (int nt = 0; nt < 8; nt++) {
            const int col = (lane & 3) * 2 + nt * 8;
            uint32_t hi, lo;
            split_pack_h(o[nt][hh*2] * inv, o[nt][hh*2+1] * inv, hi, lo);
            *(uint32_t*)&g_cx_hi[rbase + col] = hi;
            *(uint32_t*)&g_cx_lo[rbase + col] = lo;
        }
    }
}

// ---------------------------------------------------------------------------
extern "C" void kernel_launch(void* const* d_in, const int* in_sizes, int n_in,
                              void* d_out, int out_size)
{
    const float* x     = (const float*)d_in[0];
    const float* w_qkv = (const float*)d_in[1];
    const float* b_qkv = (const float*)d_in[2];
    const float* w_out = (const float*)d_in[3];
    const float* b_out = (const float*)d_in[4];
    float* out = (float*)d_out;

    static bool attr_set = false;
    if (!attr_set) {
        cudaFuncSetAttribute(tc_gemm, cudaFuncAttributeMaxDynamicSharedMemorySize, GEMM_SMEM);
        cudaFuncSetAttribute(attn_kernel, cudaFuncAttributeMaxDynamicSharedMemorySize, ATTN_SMEM);
        attr_set = true;
    }

    split_all_kernel<<<(N4_ALL + 255)/256, 256>>>(x, w_qkv, w_out);
    tc_gemm<<<dim3(3*EMB/128, MTOT/128), 256, GEMM_SMEM>>>(b_qkv, nullptr, 0);
    attn_kernel<<<dim3(BH, SEQ/128), 256, ATTN_SMEM>>>();
    tc_gemm<<<dim3(EMB/128, MTOT/128), 256, GEMM_SMEM>>>(b_out, out, 1);
}

// round 14
// speedup vs baseline: 1.7093x; 1.2104x over previous
#include <cuda_runtime.h>
#include <cuda_fp16.h>
#include <cstdint>

#define BATCH   2
#define SEQ     2048
#define EMB     1024
#define HEADS   16
#define HDIM    64
#define MTOT    (BATCH*SEQ)        // 4096
#define BH      (BATCH*HEADS)      // 32
#define QSCALE  (0.125f * 1.4426950408889634f)   // SCALE * log2(e)

// ---------------- scratch (device globals; cudaMalloc forbidden) -----------
__device__ __half g_x_hi[MTOT*EMB],  g_x_lo[MTOT*EMB];
__device__ __half g_wq_hi[3*EMB*EMB];
__device__ __half g_wo_hi[EMB*EMB];
__device__ __half g_cx_hi[MTOT*EMB];                          // ctx hi only
__device__ __half g_q_hi[BH*SEQ*HDIM], g_q_lo[BH*SEQ*HDIM];   // [bh][n][d], pre-scaled
__device__ __half g_k_hi[BH*SEQ*HDIM];                        // [bh][n][d]
__device__ __half g_vT_hi[BH*HDIM*SEQ];                       // [bh][d][n]

// ---------------- helpers --------------------------------------------------
__device__ __forceinline__ uint32_t smem_u32(const void* p) {
    uint32_t a;
    asm("{ .reg .u64 t; cvta.to.shared.u64 t, %1; cvt.u32.u64 %0, t; }"
        : "=r"(a) : "l"(p));
    return a;
}
#define SW(off)   ((uint32_t)(off) ^ ((((uint32_t)(off)) >> 3) & 0x70))   // SW128
#define SW64(off) ((uint32_t)(off) ^ ((((uint32_t)(off)) >> 3) & 0x30))   // SW64

__device__ __forceinline__ void ldsm_x4(uint32_t& r0, uint32_t& r1,
                                        uint32_t& r2, uint32_t& r3, uint32_t addr) {
    asm volatile("ldmatrix.sync.aligned.m8n8.x4.shared.b16 {%0,%1,%2,%3}, [%4];"
                 : "=r"(r0), "=r"(r1), "=r"(r2), "=r"(r3) : "r"(addr));
}
__device__ __forceinline__ void mma16816(float c[4],
                                         uint32_t a0, uint32_t a1, uint32_t a2, uint32_t a3,
                                         uint32_t b0, uint32_t b1) {
    asm volatile("mma.sync.aligned.m16n8k16.row.col.f32.f16.f16.f32 "
                 "{%0,%1,%2,%3}, {%4,%5,%6,%7}, {%8,%9}, {%0,%1,%2,%3};"
                 : "+f"(c[0]), "+f"(c[1]), "+f"(c[2]), "+f"(c[3])
                 : "r"(a0), "r"(a1), "r"(a2), "r"(a3), "r"(b0), "r"(b1));
}
__device__ __forceinline__ void cp16(uint32_t dst, const void* src) {
    asm volatile("cp.async.cg.shared.global [%0], [%1], 16;" :: "r"(dst), "l"(src));
}
#define CP_COMMIT()  asm volatile("cp.async.commit_group;" ::: "memory")
#define CP_WAIT0()   asm volatile("cp.async.wait_group 0;" ::: "memory")
#define CP_WAIT1()   asm volatile("cp.async.wait_group 1;" ::: "memory")
#define CP_WAIT2()   asm volatile("cp.async.wait_group 2;" ::: "memory")

__device__ __forceinline__ void split_pack_h(float v0, float v1, uint32_t& hi, uint32_t& lo) {
    __half h0 = __float2half_rn(v0), h1 = __float2half_rn(v1);
    __half l0 = __float2half_rn(v0 - __half2float(h0));
    __half l1 = __float2half_rn(v1 - __half2float(h1));
    hi = (uint32_t)__half_as_ushort(h0) | ((uint32_t)__half_as_ushort(h1) << 16);
    lo = (uint32_t)__half_as_ushort(l0) | ((uint32_t)__half_as_ushort(l1) << 16);
}
__device__ __forceinline__ uint32_t pack_h(float v0, float v1) {
    return (uint32_t)__half_as_ushort(__float2half_rn(v0)) |
           ((uint32_t)__half_as_ushort(__float2half_rn(v1)) << 16);
}

// ---------------------------------------------------------------------------
// Merged split: x -> fp16 hi+lo;  w_qkv, w_out -> fp16 hi only
// ---------------------------------------------------------------------------
#define N4_X   (MTOT*EMB/4)
#define N4_WQ  (3*EMB*EMB/4)
#define N4_WO  (EMB*EMB/4)
#define N4_ALL (N4_X + N4_WQ + N4_WO)

__global__ __launch_bounds__(256) void split_all_kernel(
    const float* __restrict__ x, const float* __restrict__ wq,
    const float* __restrict__ wo)
{
    int i = blockIdx.x * 256 + threadIdx.x;
    if (i >= N4_ALL) return;
    int j = i;
    if (j < N4_X) {
        float4 v = ((const float4*)x)[j];
        uint32_t h01, l01, h23, l23;
        split_pack_h(v.x, v.y, h01, l01);
        split_pack_h(v.z, v.w, h23, l23);
        ((uint2*)g_x_hi)[j] = make_uint2(h01, h23);
        ((uint2*)g_x_lo)[j] = make_uint2(l01, l23);
    } else if ((j -= N4_X) < N4_WQ) {
        float4 v = ((const float4*)wq)[j];
        ((uint2*)g_wq_hi)[j] = make_uint2(pack_h(v.x, v.y), pack_h(v.z, v.w));
    } else {
        j -= N4_WQ;
        float4 v = ((const float4*)wo)[j];
        ((uint2*)g_wo_hi)[j] = make_uint2(pack_h(v.x, v.y), pack_h(v.z, v.w));
    }
}

// ---------------------------------------------------------------------------
// HMMA fp16 GEMM. mode 0 (qkv): D = (Ah+Al)*Bh^T, 2 passes, scatter Q/K/V.
// mode 1 (out):  D = Ah*Bh^T, 1 pass (ctx hi only), fp32 out.
// BK=32 (SW64). Stage 24KB {Ah@0, Al@8K, Bh@16K} x3. 2 CTAs/SM.
// ---------------------------------------------------------------------------
#define GSTAGE    24576
#define GEMM_SMEM (3*GSTAGE)

__global__ __launch_bounds__(256, 2) void tc_gemm(
    const float* __restrict__ bias, float* __restrict__ out, int mode)
{
    extern __shared__ char sb[];
    const uint32_t sbu = smem_u32(sb);
    const int tid = threadIdx.x;
    const int wid = tid >> 5, lane = tid & 31;
    const int wm = wid >> 2, wn = wid & 3;
    const int m0 = blockIdx.y * 128, n0 = blockIdx.x * 128;

    const char *Ahg, *Alg, *Bhg;
    if (mode == 0) {
        Ahg = (const char*)(g_x_hi  + (size_t)m0 * EMB);
        Alg = (const char*)(g_x_lo  + (size_t)m0 * EMB);
        Bhg = (const char*)(g_wq_hi + (size_t)n0 * EMB);
    } else {
        Ahg = (const char*)(g_cx_hi + (size_t)m0 * EMB);
        Alg = nullptr;
        Bhg = (const char*)(g_wo_hi + (size_t)n0 * EMB);
    }

    float acc[4][4][4];
#pragma unroll
    for (int i = 0; i < 4; i++)
#pragma unroll
        for (int j = 0; j < 4; j++)
#pragma unroll
            for (int e = 0; e < 4; e++) acc[i][j][e] = 0.f;

    const int a_r  = (lane & 7) + ((lane >> 3) & 1) * 8;
    const int a_kb = (lane >> 4) * 16;
    const int b_r  = (lane & 7) + (lane >> 4) * 8;
    const int b_kb = ((lane >> 3) & 1) * 16;

    auto load_stage = [&](int c, int s) {
        const uint32_t base = sbu + s * GSTAGE;
#pragma unroll
        for (int it = 0; it < 2; it++) {
            const int idx = tid + it * 256;
            const int r = idx >> 2, cc = (idx & 3) * 16;
            const uint32_t sw = SW64(r * 64 + cc);
            const size_t g = (size_t)r * 2048 + (size_t)c * 64 + cc;
            cp16(base + sw,          Ahg + g);
            if (mode == 0) cp16(base + 8192 + sw, Alg + g);
            cp16(base + 16384 + sw,  Bhg + g);
        }
    };

    load_stage(0, 0); CP_COMMIT();
    load_stage(1, 1); CP_COMMIT();

    for (int c = 0; c < 32; c++) {
        const int buf = c % 3;
        if (c + 2 < 32) { load_stage(c + 2, (c + 2) % 3); CP_COMMIT(); CP_WAIT2(); }
        else if (c == 30) { CP_WAIT1(); }
        else              { CP_WAIT0(); }
        __syncthreads();

        const uint32_t Ah = sbu + buf * GSTAGE;
        const uint32_t Al = Ah + 8192, Bh = Ah + 16384;
#pragma unroll
        for (int ks = 0; ks < 2; ks++) {
            const int kb = ks * 32;
            uint32_t ah[4][4], bh[2][4];
#pragma unroll
            for (int mt = 0; mt < 4; mt++) {
                const int row = wm * 64 + mt * 16 + a_r;
                ldsm_x4(ah[mt][0], ah[mt][1], ah[mt][2], ah[mt][3],
                        Ah + SW64(row * 64 + kb + a_kb));
            }
#pragma unroll
            for (int p = 0; p < 2; p++) {
                const int row = wn * 32 + p * 16 + b_r;
                ldsm_x4(bh[p][0], bh[p][1], bh[p][2], bh[p][3],
                        Bh + SW64(row * 64 + kb + b_kb));
            }
            // pass 1: Ah x Bh
#pragma unroll
            for (int mt = 0; mt < 4; mt++)
#pragma unroll
                for (int p = 0; p < 2; p++) {
                    mma16816(acc[mt][p*2],   ah[mt][0], ah[mt][1], ah[mt][2], ah[mt][3], bh[p][0], bh[p][1]);
                    mma16816(acc[mt][p*2+1], ah[mt][0], ah[mt][1], ah[mt][2], ah[mt][3], bh[p][2], bh[p][3]);
                }
            // pass 2: Al x Bh (qkv GEMM only)
            if (mode == 0) {
                uint32_t al[4][4];
#pragma unroll
                for (int mt = 0; mt < 4; mt++) {
                    const int row = wm * 64 + mt * 16 + a_r;
                    ldsm_x4(al[mt][0], al[mt][1], al[mt][2], al[mt][3],
                            Al + SW64(row * 64 + kb + a_kb));
                }
#pragma unroll
                for (int mt = 0; mt < 4; mt++)
#pragma unroll
                    for (int p = 0; p < 2; p++) {
                        mma16816(acc[mt][p*2],   al[mt][0], al[mt][1], al[mt][2], al[mt][3], bh[p][0], bh[p][1]);
                        mma16816(acc[mt][p*2+1], al[mt][0], al[mt][1], al[mt][2], al[mt][3], bh[p][2], bh[p][3]);
                    }
            }
        }
        __syncthreads();
    }

    const int rbase = m0 + wm * 64 + (lane >> 2);
    const int cbase = n0 + wn * 32 + (lane & 3) * 2;
#pragma unroll
    for (int mt = 0; mt < 4; mt++) {
#pragma unroll
        for (int nt = 0; nt < 4; nt++) {
            const int col = cbase + nt * 8;
            const float bx = bias[col], by = bias[col + 1];
#pragma unroll
            for (int half = 0; half < 2; half++) {
                const int row = rbase + mt * 16 + half * 8;
                float v0 = acc[mt][nt][half * 2 + 0] + bx;
                float v1 = acc[mt][nt][half * 2 + 1] + by;
                if (mode == 1) {
                    *(float2*)(out + (size_t)row * EMB + col) = make_float2(v0, v1);
                } else {
                    const int b = row >> 11, n = row & 2047;
                    const int which = col >> 10;
                    const int hd = col & 1023;
                    const int h = hd >> 6, d = hd & 63;
                    const int bhi = (b << 4) + h;
                    if (which == 0) {
                        uint32_t hi, lo;
                        split_pack_h(v0 * QSCALE, v1 * QSCALE, hi, lo);
                        const size_t off = ((size_t)bhi * SEQ + n) * HDIM + d;
                        *(uint32_t*)&g_q_hi[off] = hi;
                        *(uint32_t*)&g_q_lo[off] = lo;
                    } else if (which == 1) {
                        const size_t off = ((size_t)bhi * SEQ + n) * HDIM + d;
                        *(uint32_t*)&g_k_hi[off] = pack_h(v0, v1);
                    } else {
                        const size_t o0 = ((size_t)bhi * HDIM + d) * SEQ + n;
                        const size_t o1 = ((size_t)bhi * HDIM + d + 1) * SEQ + n;
                        g_vT_hi[o0] = __float2half_rn(v0);
                        g_vT_hi[o1] = __float2half_rn(v1);
                    }
                }
            }
        }
    }
}

// ---------------------------------------------------------------------------
// HMMA flash attention: S = (Qh+Ql)*Kh (2 passes);  O += Ph*Vh (1 pass).
// Register-resident P, log2-domain softmax (exp2f). Ctx written hi-only.
// Smem: Qh@0 Ql@16K | stage s@32K+s*32K {Kh 16K, VTh 2x8K}. 3 stages. 128KB.
// ---------------------------------------------------------------------------
#define ASTG      32768
#define AS_KV     32768
#define ATTN_SMEM (AS_KV + 3*ASTG)

__global__ __launch_bounds__(256) void attn_kernel()
{
    extern __shared__ char sb[];
    const uint32_t sbu = smem_u32(sb);
    const int tid = threadIdx.x;
    const int wid = tid >> 5, lane = tid & 31;
    const int bh = blockIdx.x;
    const int q0 = blockIdx.y * 128;

    const int a_r  = (lane & 7) + ((lane >> 3) & 1) * 8;
    const int a_kb = (lane >> 4) * 16;
    const int b_r  = (lane & 7) + (lane >> 4) * 8;
    const int b_kb = ((lane >> 3) & 1) * 16;

    // ---- Q tile (hi+lo) ----
    {
        const char* qh = (const char*)(g_q_hi + ((size_t)bh * SEQ + q0) * HDIM);
        const char* ql = (const char*)(g_q_lo + ((size_t)bh * SEQ + q0) * HDIM);
#pragma unroll
        for (int it = 0; it < 4; it++) {
            const int idx = tid + it * 256;
            const int r = idx >> 3, in = (idx & 7) * 16;
            const uint32_t sw = SW(r * 128 + in);
            cp16(sbu + sw,         qh + r * 128 + in);
            cp16(sbu + 16384 + sw, ql + r * 128 + in);
        }
    }

    auto load_stage = [&](int kt, int s) {
        const uint32_t base = sbu + AS_KV + s * ASTG;
        const char* kh = (const char*)(g_k_hi + ((size_t)bh * SEQ + kt * 128) * HDIM);
#pragma unroll
        for (int it = 0; it < 4; it++) {
            const int idx = tid + it * 256;
            const int r = idx >> 3, in = (idx & 7) * 16;
            cp16(base + SW(r * 128 + in), kh + r * 128 + in);
        }
        const char* vh = (const char*)(g_vT_hi + (size_t)bh * HDIM * SEQ) + (size_t)kt * 256;
#pragma unroll
        for (int it = 0; it < 4; it++) {
            const int idx = tid + it * 256;
            const int r = idx >> 4;
            const int inner = (idx & 15) * 16;
            const int half = inner >> 7, in128 = inner & 127;
            cp16(base + 16384 + half * 8192 + SW(r * 128 + in128),
                 vh + (size_t)r * 4096 + inner);
        }
    };

    load_stage(0, 0); CP_COMMIT();
    load_stage(1, 1); CP_COMMIT();

    float o[8][4];
    float mi[2], li[2];
#pragma unroll
    for (int i = 0; i < 8; i++)
#pragma unroll
        for (int e = 0; e < 4; e++) o[i][e] = 0.f;
    mi[0] = mi[1] = -1e30f;
    li[0] = li[1] = 0.f;

    const int arow = wid * 16 + a_r;

    for (int kt = 0; kt < 16; kt++) {
        const int buf = kt % 3;
        if (kt + 2 < 16) { load_stage(kt + 2, (kt + 2) % 3); CP_COMMIT(); CP_WAIT2(); }
        else if (kt == 14) { CP_WAIT1(); }
        else               { CP_WAIT0(); }
        __syncthreads();

        const uint32_t Kh = sbu + AS_KV + buf * ASTG;
        const uint32_t Vh = Kh + 16384;

        // ---- S = (Qh+Ql)*Kh ----
        float s[16][4];
#pragma unroll
        for (int i = 0; i < 16; i++)
#pragma unroll
            for (int e = 0; e < 4; e++) s[i][e] = 0.f;

#pragma unroll
        for (int ks = 0; ks < 4; ks++) {
            const int kb = ks * 32;
            uint32_t ah0, ah1, ah2, ah3, al0, al1, al2, al3;
            ldsm_x4(ah0, ah1, ah2, ah3, sbu +         SW(arow * 128 + kb + a_kb));
            ldsm_x4(al0, al1, al2, al3, sbu + 16384 + SW(arow * 128 + kb + a_kb));
#pragma unroll
            for (int p = 0; p < 8; p++) {
                const int row = p * 16 + b_r;
                uint32_t t0, t1, t2, t3;
                ldsm_x4(t0, t1, t2, t3, Kh + SW(row * 128 + kb + b_kb));
                mma16816(s[p*2],   ah0, ah1, ah2, ah3, t0, t1);
                mma16816(s[p*2+1], ah0, ah1, ah2, ah3, t2, t3);
                mma16816(s[p*2],   al0, al1, al2, al3, t0, t1);
                mma16816(s[p*2+1], al0, al1, al2, al3, t2, t3);
            }
        }

        // ---- online softmax in log2 domain ----
#pragma unroll
        for (int h = 0; h < 2; h++) {
            float rm = -1e30f;
#pragma unroll
            for (int nt = 0; nt < 16; nt++)
                rm = fmaxf(rm, fmaxf(s[nt][h*2], s[nt][h*2+1]));
            rm = fmaxf(rm, __shfl_xor_sync(0xffffffffu, rm, 1));
            rm = fmaxf(rm, __shfl_xor_sync(0xffffffffu, rm, 2));
            const float m2 = fmaxf(mi[h], rm);
            const float alpha = exp2f(mi[h] - m2);
            float rs = 0.f;
#pragma unroll
            for (int nt = 0; nt < 16; nt++) {
                const float p0 = exp2f(s[nt][h*2]   - m2);
                const float p1 = exp2f(s[nt][h*2+1] - m2);
                s[nt][h*2] = p0; s[nt][h*2+1] = p1;
                rs += p0 + p1;
            }
            rs += __shfl_xor_sync(0xffffffffu, rs, 1);
            rs += __shfl_xor_sync(0xffffffffu, rs, 2);
            li[h] = li[h] * alpha + rs;
            mi[h] = m2;
#pragma unroll
            for (int nt = 0; nt < 8; nt++) {
                o[nt][h*2]   *= alpha;
                o[nt][h*2+1] *= alpha;
            }
        }

        // ---- O += Ph*Vh, P from registers (fp16 hi only) ----
#pragma unroll
        for (int kc = 0; kc < 8; kc++) {
            const int half = kc >> 2;
            const int koff = (kc & 3) * 32;
            const uint32_t ah0 = pack_h(s[2*kc][0],   s[2*kc][1]);
            const uint32_t ah1 = pack_h(s[2*kc][2],   s[2*kc][3]);
            const uint32_t ah2 = pack_h(s[2*kc+1][0], s[2*kc+1][1]);
            const uint32_t ah3 = pack_h(s[2*kc+1][2], s[2*kc+1][3]);
#pragma unroll
            for (int p = 0; p < 4; p++) {
                const int row = p * 16 + b_r;
                uint32_t t0, t1, t2, t3;
                ldsm_x4(t0, t1, t2, t3, Vh + half * 8192 + SW(row * 128 + koff + b_kb));
                mma16816(o[p*2],   ah0, ah1, ah2, ah3, t0, t1);
                mma16816(o[p*2+1], ah0, ah1, ah2, ah3, t2, t3);
            }
        }
        __syncthreads();
    }

    // ---- epilogue: normalize, fp16 hi ctx in [B,N,H*D] ----
    const int b = bh >> 4, h = bh & 15;
#pragma unroll
    for (int hh = 0; hh < 2; hh++) {
        const float inv = 1.f / li[hh];
        const int row = q0 + wid * 16 + (lane >> 2) + hh * 8;
        const size_t rbase = ((size_t)b * SEQ + row) * EMB + h * HDIM;
#pragma unroll
        for (int nt = 0; nt < 8; nt++) {
            const int col = (lane & 3) * 2 + nt * 8;
            *(uint32_t*)&g_cx_hi[rbase + col] = pack_h(o[nt][hh*2] * inv, o[nt][hh*2+1] * inv);
        }
    }
}

// ---------------------------------------------------------------------------
extern "C" void kernel_launch(void* const* d_in, const int* in_sizes, int n_in,
                              void* d_out, int out_size)
{
    const float* x     = (const float*)d_in[0];
    const float* w_qkv = (const float*)d_in[1];
    const float* b_qkv = (const float*)d_in[2];
    const float* w_out = (const float*)d_in[3];
    const float* b_out = (const float*)d_in[4];
    float* out = (float*)d_out;

    static bool attr_set = false;
    if (!attr_set) {
        cudaFuncSetAttribute(tc_gemm, cudaFuncAttributeMaxDynamicSharedMemorySize, GEMM_SMEM);
        cudaFuncSetAttribute(attn_kernel, cudaFuncAttributeMaxDynamicSharedMemorySize, ATTN_SMEM);
        attr_set = true;
    }

    split_all_kernel<<<(N4_ALL + 255)/256, 256>>>(x, w_qkv, w_out);
    tc_gemm<<<dim3(3*EMB/128, MTOT/128), 256, GEMM_SMEM>>>(b_qkv, nullptr, 0);
    attn_kernel<<<dim3(BH, SEQ/128), 256, ATTN_SMEM>>>();
    tc_gemm<<<dim3(EMB/128, MTOT/128), 256, GEMM_SMEM>>>(b_out, out, 1);
}

// round 15
// speedup vs baseline: 2.0279x; 1.1864x over previous
#include <cuda_runtime.h>
#include <cuda_fp16.h>
#include <cstdint>

#define BATCH   2
#define SEQ     2048
#define EMB     1024
#define HEADS   16
#define HDIM    64
#define MTOT    (BATCH*SEQ)        // 4096
#define BH      (BATCH*HEADS)      // 32
#define QSCALE  (0.125f * 1.4426950408889634f)   // SCALE * log2(e)

// ---------------- scratch (device globals; cudaMalloc forbidden) -----------
__device__ __half g_x_hi[MTOT*EMB],  g_x_lo[MTOT*EMB];
__device__ __half g_wq_hi[3*EMB*EMB];
__device__ __half g_wo_hi[EMB*EMB];
__device__ __half g_cx_hi[MTOT*EMB];                          // ctx hi only
__device__ __half g_q_hi[BH*SEQ*HDIM];                        // [bh][n][d], pre-scaled, hi only
__device__ __half g_k_hi[BH*SEQ*HDIM];                        // [bh][n][d]
__device__ __half g_vT_hi[BH*HDIM*SEQ];                       // [bh][d][n]

// ---------------- helpers --------------------------------------------------
__device__ __forceinline__ uint32_t smem_u32(const void* p) {
    uint32_t a;
    asm("{ .reg .u64 t; cvta.to.shared.u64 t, %1; cvt.u32.u64 %0, t; }"
        : "=r"(a) : "l"(p));
    return a;
}
#define SW(off)   ((uint32_t)(off) ^ ((((uint32_t)(off)) >> 3) & 0x70))   // SW128
#define SW64(off) ((uint32_t)(off) ^ ((((uint32_t)(off)) >> 3) & 0x30))   // SW64

__device__ __forceinline__ void ldsm_x4(uint32_t& r0, uint32_t& r1,
                                        uint32_t& r2, uint32_t& r3, uint32_t addr) {
    asm volatile("ldmatrix.sync.aligned.m8n8.x4.shared.b16 {%0,%1,%2,%3}, [%4];"
                 : "=r"(r0), "=r"(r1), "=r"(r2), "=r"(r3) : "r"(addr));
}
__device__ __forceinline__ void mma16816(float c[4],
                                         uint32_t a0, uint32_t a1, uint32_t a2, uint32_t a3,
                                         uint32_t b0, uint32_t b1) {
    asm volatile("mma.sync.aligned.m16n8k16.row.col.f32.f16.f16.f32 "
                 "{%0,%1,%2,%3}, {%4,%5,%6,%7}, {%8,%9}, {%0,%1,%2,%3};"
                 : "+f"(c[0]), "+f"(c[1]), "+f"(c[2]), "+f"(c[3])
                 : "r"(a0), "r"(a1), "r"(a2), "r"(a3), "r"(b0), "r"(b1));
}
__device__ __forceinline__ void cp16(uint32_t dst, const void* src) {
    asm volatile("cp.async.cg.shared.global [%0], [%1], 16;" :: "r"(dst), "l"(src));
}
#define CP_COMMIT()  asm volatile("cp.async.commit_group;" ::: "memory")
#define CP_WAIT0()   asm volatile("cp.async.wait_group 0;" ::: "memory")
#define CP_WAIT1()   asm volatile("cp.async.wait_group 1;" ::: "memory")
#define CP_WAIT2()   asm volatile("cp.async.wait_group 2;" ::: "memory")

__device__ __forceinline__ void split_pack_h(float v0, float v1, uint32_t& hi, uint32_t& lo) {
    __half h0 = __float2half_rn(v0), h1 = __float2half_rn(v1);
    __half l0 = __float2half_rn(v0 - __half2float(h0));
    __half l1 = __float2half_rn(v1 - __half2float(h1));
    hi = (uint32_t)__half_as_ushort(h0) | ((uint32_t)__half_as_ushort(h1) << 16);
    lo = (uint32_t)__half_as_ushort(l0) | ((uint32_t)__half_as_ushort(l1) << 16);
}
__device__ __forceinline__ uint32_t pack_h(float v0, float v1) {
    return (uint32_t)__half_as_ushort(__float2half_rn(v0)) |
           ((uint32_t)__half_as_ushort(__float2half_rn(v1)) << 16);
}

// ---------------------------------------------------------------------------
// Merged split: x -> fp16 hi+lo;  w_qkv, w_out -> fp16 hi only
// ---------------------------------------------------------------------------
#define N4_X   (MTOT*EMB/4)
#define N4_WQ  (3*EMB*EMB/4)
#define N4_WO  (EMB*EMB/4)
#define N4_ALL (N4_X + N4_WQ + N4_WO)

__global__ __launch_bounds__(256) void split_all_kernel(
    const float* __restrict__ x, const float* __restrict__ wq,
    const float* __restrict__ wo)
{
    int i = blockIdx.x * 256 + threadIdx.x;
    if (i >= N4_ALL) return;
    int j = i;
    if (j < N4_X) {
        float4 v = ((const float4*)x)[j];
        uint32_t h01, l01, h23, l23;
        split_pack_h(v.x, v.y, h01, l01);
        split_pack_h(v.z, v.w, h23, l23);
        ((uint2*)g_x_hi)[j] = make_uint2(h01, h23);
        ((uint2*)g_x_lo)[j] = make_uint2(l01, l23);
    } else if ((j -= N4_X) < N4_WQ) {
        float4 v = ((const float4*)wq)[j];
        ((uint2*)g_wq_hi)[j] = make_uint2(pack_h(v.x, v.y), pack_h(v.z, v.w));
    } else {
        j -= N4_WQ;
        float4 v = ((const float4*)wo)[j];
        ((uint2*)g_wo_hi)[j] = make_uint2(pack_h(v.x, v.y), pack_h(v.z, v.w));
    }
}

// ---------------------------------------------------------------------------
// HMMA fp16 GEMM.
// mode 0 (qkv): Q/K column-blocks (n0<2048): D = (Ah+Al)*Bh^T (2 passes);
//               V column-blocks (n0>=2048):  D = Ah*Bh^T (1 pass).
// mode 1 (out): D = Ah*Bh^T (1 pass), fp32 out.
// BK=32 (SW64). Stage 24KB {Ah@0, Al@8K, Bh@16K} x3. 2 CTAs/SM.
// ---------------------------------------------------------------------------
#define GSTAGE    24576
#define GEMM_SMEM (3*GSTAGE)

__global__ __launch_bounds__(256, 2) void tc_gemm(
    const float* __restrict__ bias, float* __restrict__ out, int mode)
{
    extern __shared__ char sb[];
    const uint32_t sbu = smem_u32(sb);
    const int tid = threadIdx.x;
    const int wid = tid >> 5, lane = tid & 31;
    const int wm = wid >> 2, wn = wid & 3;
    const int m0 = blockIdx.y * 128, n0 = blockIdx.x * 128;
    const bool twopass = (mode == 0) && (n0 < 2048);   // Q/K need the Al pass; V doesn't

    const char *Ahg, *Alg, *Bhg;
    if (mode == 0) {
        Ahg = (const char*)(g_x_hi  + (size_t)m0 * EMB);
        Alg = (const char*)(g_x_lo  + (size_t)m0 * EMB);
        Bhg = (const char*)(g_wq_hi + (size_t)n0 * EMB);
    } else {
        Ahg = (const char*)(g_cx_hi + (size_t)m0 * EMB);
        Alg = nullptr;
        Bhg = (const char*)(g_wo_hi + (size_t)n0 * EMB);
    }

    float acc[4][4][4];
#pragma unroll
    for (int i = 0; i < 4; i++)
#pragma unroll
        for (int j = 0; j < 4; j++)
#pragma unroll
            for (int e = 0; e < 4; e++) acc[i][j][e] = 0.f;

    const int a_r  = (lane & 7) + ((lane >> 3) & 1) * 8;
    const int a_kb = (lane >> 4) * 16;
    const int b_r  = (lane & 7) + (lane >> 4) * 8;
    const int b_kb = ((lane >> 3) & 1) * 16;

    auto load_stage = [&](int c, int s) {
        const uint32_t base = sbu + s * GSTAGE;
#pragma unroll
        for (int it = 0; it < 2; it++) {
            const int idx = tid + it * 256;
            const int r = idx >> 2, cc = (idx & 3) * 16;
            const uint32_t sw = SW64(r * 64 + cc);
            const size_t g = (size_t)r * 2048 + (size_t)c * 64 + cc;
            cp16(base + sw,          Ahg + g);
            if (twopass) cp16(base + 8192 + sw, Alg + g);
            cp16(base + 16384 + sw,  Bhg + g);
        }
    };

    load_stage(0, 0); CP_COMMIT();
    load_stage(1, 1); CP_COMMIT();

    for (int c = 0; c < 32; c++) {
        const int buf = c % 3;
        if (c + 2 < 32) { load_stage(c + 2, (c + 2) % 3); CP_COMMIT(); CP_WAIT2(); }
        else if (c == 30) { CP_WAIT1(); }
        else              { CP_WAIT0(); }
        __syncthreads();

        const uint32_t Ah = sbu + buf * GSTAGE;
        const uint32_t Al = Ah + 8192, Bh = Ah + 16384;
#pragma unroll
        for (int ks = 0; ks < 2; ks++) {
            const int kb = ks * 32;
            uint32_t ah[4][4], bh[2][4];
#pragma unroll
            for (int mt = 0; mt < 4; mt++) {
                const int row = wm * 64 + mt * 16 + a_r;
                ldsm_x4(ah[mt][0], ah[mt][1], ah[mt][2], ah[mt][3],
                        Ah + SW64(row * 64 + kb + a_kb));
            }
#pragma unroll
            for (int p = 0; p < 2; p++) {
                const int row = wn * 32 + p * 16 + b_r;
                ldsm_x4(bh[p][0], bh[p][1], bh[p][2], bh[p][3],
                        Bh + SW64(row * 64 + kb + b_kb));
            }
            // pass 1: Ah x Bh
#pragma unroll
            for (int mt = 0; mt < 4; mt++)
#pragma unroll
                for (int p = 0; p < 2; p++) {
                    mma16816(acc[mt][p*2],   ah[mt][0], ah[mt][1], ah[mt][2], ah[mt][3], bh[p][0], bh[p][1]);
                    mma16816(acc[mt][p*2+1], ah[mt][0], ah[mt][1], ah[mt][2], ah[mt][3], bh[p][2], bh[p][3]);
                }
            // pass 2: Al x Bh (Q/K columns only)
            if (twopass) {
                uint32_t al[4][4];
#pragma unroll
                for (int mt = 0; mt < 4; mt++) {
                    const int row = wm * 64 + mt * 16 + a_r;
                    ldsm_x4(al[mt][0], al[mt][1], al[mt][2], al[mt][3],
                            Al + SW64(row * 64 + kb + a_kb));
                }
#pragma unroll
                for (int mt = 0; mt < 4; mt++)
#pragma unroll
                    for (int p = 0; p < 2; p++) {
                        mma16816(acc[mt][p*2],   al[mt][0], al[mt][1], al[mt][2], al[mt][3], bh[p][0], bh[p][1]);
                        mma16816(acc[mt][p*2+1], al[mt][0], al[mt][1], al[mt][2], al[mt][3], bh[p][2], bh[p][3]);
                    }
            }
        }
        __syncthreads();
    }

    const int rbase = m0 + wm * 64 + (lane >> 2);
    const int cbase = n0 + wn * 32 + (lane & 3) * 2;
#pragma unroll
    for (int mt = 0; mt < 4; mt++) {
#pragma unroll
        for (int nt = 0; nt < 4; nt++) {
            const int col = cbase + nt * 8;
            const float bx = bias[col], by = bias[col + 1];
#pragma unroll
            for (int half = 0; half < 2; half++) {
                const int row = rbase + mt * 16 + half * 8;
                float v0 = acc[mt][nt][half * 2 + 0] + bx;
                float v1 = acc[mt][nt][half * 2 + 1] + by;
                if (mode == 1) {
                    *(float2*)(out + (size_t)row * EMB + col) = make_float2(v0, v1);
                } else {
                    const int b = row >> 11, n = row & 2047;
                    const int which = col >> 10;
                    const int hd = col & 1023;
                    const int h = hd >> 6, d = hd & 63;
                    const int bhi = (b << 4) + h;
                    if (which == 0) {
                        const size_t off = ((size_t)bhi * SEQ + n) * HDIM + d;
                        *(uint32_t*)&g_q_hi[off] = pack_h(v0 * QSCALE, v1 * QSCALE);
                    } else if (which == 1) {
                        const size_t off = ((size_t)bhi * SEQ + n) * HDIM + d;
                        *(uint32_t*)&g_k_hi[off] = pack_h(v0, v1);
                    } else {
                        const size_t o0 = ((size_t)bhi * HDIM + d) * SEQ + n;
                        const size_t o1 = ((size_t)bhi * HDIM + d + 1) * SEQ + n;
                        g_vT_hi[o0] = __float2half_rn(v0);
                        g_vT_hi[o1] = __float2half_rn(v1);
                    }
                }
            }
        }
    }
}

// ---------------------------------------------------------------------------
// HMMA flash attention: S = Qh*Kh (1 pass);  O += Ph*Vh (1 pass).
// Register-resident P, log2-domain softmax (exp2f). Ctx written hi-only.
// Smem: Qh@0(16K) | stage s@16K+s*32K {Kh 16K, VTh 2x8K}. 3 stages. 112KB.
// 2 CTAs/SM (224KB smem, regs <= 128).
// ---------------------------------------------------------------------------
#define ASTG      32768
#define AS_KV     16384
#define ATTN_SMEM (AS_KV + 3*ASTG)

__global__ __launch_bounds__(256, 2) void attn_kernel()
{
    extern __shared__ char sb[];
    const uint32_t sbu = smem_u32(sb);
    const int tid = threadIdx.x;
    const int wid = tid >> 5, lane = tid & 31;
    const int bh = blockIdx.x;
    const int q0 = blockIdx.y * 128;

    const int a_r  = (lane & 7) + ((lane >> 3) & 1) * 8;
    const int a_kb = (lane >> 4) * 16;
    const int b_r  = (lane & 7) + (lane >> 4) * 8;
    const int b_kb = ((lane >> 3) & 1) * 16;

    // ---- Q tile (hi only) ----
    {
        const char* qh = (const char*)(g_q_hi + ((size_t)bh * SEQ + q0) * HDIM);
#pragma unroll
        for (int it = 0; it < 4; it++) {
            const int idx = tid + it * 256;
            const int r = idx >> 3, in = (idx & 7) * 16;
            cp16(sbu + SW(r * 128 + in), qh + r * 128 + in);
        }
    }

    auto load_stage = [&](int kt, int s) {
        const uint32_t base = sbu + AS_KV + s * ASTG;
        const char* kh = (const char*)(g_k_hi + ((size_t)bh * SEQ + kt * 128) * HDIM);
#pragma unroll
        for (int it = 0; it < 4; it++) {
            const int idx = tid + it * 256;
            const int r = idx >> 3, in = (idx & 7) * 16;
            cp16(base + SW(r * 128 + in), kh + r * 128 + in);
        }
        const char* vh = (const char*)(g_vT_hi + (size_t)bh * HDIM * SEQ) + (size_t)kt * 256;
#pragma unroll
        for (int it = 0; it < 4; it++) {
            const int idx = tid + it * 256;
            const int r = idx >> 4;
            const int inner = (idx & 15) * 16;
            const int half = inner >> 7, in128 = inner & 127;
            cp16(base + 16384 + half * 8192 + SW(r * 128 + in128),
                 vh + (size_t)r * 4096 + inner);
        }
    };

    load_stage(0, 0); CP_COMMIT();
    load_stage(1, 1); CP_COMMIT();

    float o[8][4];
    float mi[2], li[2];
#pragma unroll
    for (int i = 0; i < 8; i++)
#pragma unroll
        for (int e = 0; e < 4; e++) o[i][e] = 0.f;
    mi[0] = mi[1] = -1e30f;
    li[0] = li[1] = 0.f;

    const int arow = wid * 16 + a_r;

    for (int kt = 0; kt < 16; kt++) {
        const int buf = kt % 3;
        if (kt + 2 < 16) { load_stage(kt + 2, (kt + 2) % 3); CP_COMMIT(); CP_WAIT2(); }
        else if (kt == 14) { CP_WAIT1(); }
        else               { CP_WAIT0(); }
        __syncthreads();

        const uint32_t Kh = sbu + AS_KV + buf * ASTG;
        const uint32_t Vh = Kh + 16384;

        // ---- S = Qh*Kh ----
        float s[16][4];
#pragma unroll
        for (int i = 0; i < 16; i++)
#pragma unroll
            for (int e = 0; e < 4; e++) s[i][e] = 0.f;

#pragma unroll
        for (int ks = 0; ks < 4; ks++) {
            const int kb = ks * 32;
            uint32_t ah0, ah1, ah2, ah3;
            ldsm_x4(ah0, ah1, ah2, ah3, sbu + SW(arow * 128 + kb + a_kb));
#pragma unroll
            for (int p = 0; p < 8; p++) {
                const int row = p * 16 + b_r;
                uint32_t t0, t1, t2, t3;
                ldsm_x4(t0, t1, t2, t3, Kh + SW(row * 128 + kb + b_kb));
                mma16816(s[p*2],   ah0, ah1, ah2, ah3, t0, t1);
                mma16816(s[p*2+1], ah0, ah1, ah2, ah3, t2, t3);
            }
        }

        // ---- online softmax in log2 domain ----
#pragma unroll
        for (int h = 0; h < 2; h++) {
            float rm = -1e30f;
#pragma unroll
            for (int nt = 0; nt < 16; nt++)
                rm = fmaxf(rm, fmaxf(s[nt][h*2], s[nt][h*2+1]));
            rm = fmaxf(rm, __shfl_xor_sync(0xffffffffu, rm, 1));
            rm = fmaxf(rm, __shfl_xor_sync(0xffffffffu, rm, 2));
            const float m2 = fmaxf(mi[h], rm);
            const float alpha = exp2f(mi[h] - m2);
            float rs = 0.f;
#pragma unroll
            for (int nt = 0; nt < 16; nt++) {
                const float p0 = exp2f(s[nt][h*2]   - m2);
                const float p1 = exp2f(s[nt][h*2+1] - m2);
                s[nt][h*2] = p0; s[nt][h*2+1] = p1;
                rs += p0 + p1;
            }
            rs += __shfl_xor_sync(0xffffffffu, rs, 1);
            rs += __shfl_xor_sync(0xffffffffu, rs, 2);
            li[h] = li[h] * alpha + rs;
            mi[h] = m2;
#pragma unroll
            for (int nt = 0; nt < 8; nt++) {
                o[nt][h*2]   *= alpha;
                o[nt][h*2+1] *= alpha;
            }
        }

        // ---- O += Ph*Vh, P from registers (fp16 hi only) ----
#pragma unroll
        for (int kc = 0; kc < 8; kc++) {
            const int half = kc >> 2;
            const int koff = (kc & 3) * 32;
            const uint32_t ah0 = pack_h(s[2*kc][0],   s[2*kc][1]);
            const uint32_t ah1 = pack_h(s[2*kc][2],   s[2*kc][3]);
            const uint32_t ah2 = pack_h(s[2*kc+1][0], s[2*kc+1][1]);
            const uint32_t ah3 = pack_h(s[2*kc+1][2], s[2*kc+1][3]);
#pragma unroll
            for (int p = 0; p < 4; p++) {
                const int row = p * 16 + b_r;
                uint32_t t0, t1, t2, t3;
                ldsm_x4(t0, t1, t2, t3, Vh + half * 8192 + SW(row * 128 + koff + b_kb));
                mma16816(o[p*2],   ah0, ah1, ah2, ah3, t0, t1);
                mma16816(o[p*2+1], ah0, ah1, ah2, ah3, t2, t3);
            }
        }
        __syncthreads();
    }

    // ---- epilogue: normalize, fp16 hi ctx in [B,N,H*D] ----
    const int b = bh >> 4, h = bh & 15;
#pragma unroll
    for (int hh = 0; hh < 2; hh++) {
        const float inv = 1.f / li[hh];
        const int row = q0 + wid * 16 + (lane >> 2) + hh * 8;
        const size_t rbase = ((size_t)b * SEQ + row) * EMB + h * HDIM;
#pragma unroll
        for (int nt = 0; nt < 8; nt++) {
            const int col = (lane & 3) * 2 + nt * 8;
            *(uint32_t*)&g_cx_hi[rbase + col] = pack_h(o[nt][hh*2] * inv, o[nt][hh*2+1] * inv);
        }
    }
}

// ---------------------------------------------------------------------------
extern "C" void kernel_launch(void* const* d_in, const int* in_sizes, int n_in,
                              void* d_out, int out_size)
{
    const float* x     = (const float*)d_in[0];
    const float* w_qkv = (const float*)d_in[1];
    const float* b_qkv = (const float*)d_in[2];
    const float* w_out = (const float*)d_in[3];
    const float* b_out = (const float*)d_in[4];
    float* out = (float*)d_out;

    static bool attr_set = false;
    if (!attr_set) {
        cudaFuncSetAttribute(tc_gemm, cudaFuncAttributeMaxDynamicSharedMemorySize, GEMM_SMEM);
        cudaFuncSetAttribute(attn_kernel, cudaFuncAttributeMaxDynamicSharedMemorySize, ATTN_SMEM);
        attr_set = true;
    }

    split_all_kernel<<<(N4_ALL + 255)/256, 256>>>(x, w_qkv, w_out);
    tc_gemm<<<dim3(3*EMB/128, MTOT/128), 256, GEMM_SMEM>>>(b_qkv, nullptr, 0);
    attn_kernel<<<dim3(BH, SEQ/128), 256, ATTN_SMEM>>>();
    tc_gemm<<<dim3(EMB/128, MTOT/128), 256, GEMM_SMEM>>>(b_out, out, 1);
}

// round 16
// speedup vs baseline: 2.3111x; 1.1396x over previous
#include <cuda_runtime.h>
#include <cuda_fp16.h>
#include <cstdint>

#define BATCH   2
#define SEQ     2048
#define EMB     1024
#define HEADS   16
#define HDIM    64
#define MTOT    (BATCH*SEQ)        // 4096
#define BH      (BATCH*HEADS)      // 32
#define QSCALE  (0.125f * 1.4426950408889634f)   // SCALE * log2(e)

// ---------------- scratch (device globals; cudaMalloc forbidden) -----------
__device__ __half g_x_hi[MTOT*EMB];
__device__ __half g_wq_hi[3*EMB*EMB];
__device__ __half g_wo_hi[EMB*EMB];
__device__ __half g_cx_hi[MTOT*EMB];                          // ctx hi only
__device__ __half g_q_hi[BH*SEQ*HDIM];                        // [bh][n][d], pre-scaled
__device__ __half g_k_hi[BH*SEQ*HDIM];                        // [bh][n][d]
__device__ __half g_vT_hi[BH*HDIM*SEQ];                       // [bh][d][n]

// ---------------- helpers --------------------------------------------------
__device__ __forceinline__ uint32_t smem_u32(const void* p) {
    uint32_t a;
    asm("{ .reg .u64 t; cvta.to.shared.u64 t, %1; cvt.u32.u64 %0, t; }"
        : "=r"(a) : "l"(p));
    return a;
}
#define SW(off)   ((uint32_t)(off) ^ ((((uint32_t)(off)) >> 3) & 0x70))   // SW128
#define SW64(off) ((uint32_t)(off) ^ ((((uint32_t)(off)) >> 3) & 0x30))   // SW64

__device__ __forceinline__ void ldsm_x4(uint32_t& r0, uint32_t& r1,
                                        uint32_t& r2, uint32_t& r3, uint32_t addr) {
    asm volatile("ldmatrix.sync.aligned.m8n8.x4.shared.b16 {%0,%1,%2,%3}, [%4];"
                 : "=r"(r0), "=r"(r1), "=r"(r2), "=r"(r3) : "r"(addr));
}
__device__ __forceinline__ void mma16816(float c[4],
                                         uint32_t a0, uint32_t a1, uint32_t a2, uint32_t a3,
                                         uint32_t b0, uint32_t b1) {
    asm volatile("mma.sync.aligned.m16n8k16.row.col.f32.f16.f16.f32 "
                 "{%0,%1,%2,%3}, {%4,%5,%6,%7}, {%8,%9}, {%0,%1,%2,%3};"
                 : "+f"(c[0]), "+f"(c[1]), "+f"(c[2]), "+f"(c[3])
                 : "r"(a0), "r"(a1), "r"(a2), "r"(a3), "r"(b0), "r"(b1));
}
__device__ __forceinline__ void cp16(uint32_t dst, const void* src) {
    asm volatile("cp.async.cg.shared.global [%0], [%1], 16;" :: "r"(dst), "l"(src));
}
#define CP_COMMIT()  asm volatile("cp.async.commit_group;" ::: "memory")
#define CP_WAIT0()   asm volatile("cp.async.wait_group 0;" ::: "memory")
#define CP_WAIT1()   asm volatile("cp.async.wait_group 1;" ::: "memory")
#define CP_WAIT2()   asm volatile("cp.async.wait_group 2;" ::: "memory")

__device__ __forceinline__ uint32_t pack_h(float v0, float v1) {
    return (uint32_t)__half_as_ushort(__float2half_rn(v0)) |
           ((uint32_t)__half_as_ushort(__float2half_rn(v1)) << 16);
}

// ---------------------------------------------------------------------------
// Merged convert: x, w_qkv, w_out -> fp16 (hi only) in ONE launch
// ---------------------------------------------------------------------------
#define N4_X   (MTOT*EMB/4)
#define N4_WQ  (3*EMB*EMB/4)
#define N4_WO  (EMB*EMB/4)
#define N4_ALL (N4_X + N4_WQ + N4_WO)

__global__ __launch_bounds__(256) void split_all_kernel(
    const float* __restrict__ x, const float* __restrict__ wq,
    const float* __restrict__ wo)
{
    int i = blockIdx.x * 256 + threadIdx.x;
    if (i >= N4_ALL) return;
    const float* in;
    __half* hi;
    int j = i;
    if (j < N4_X)                 { in = x;  hi = g_x_hi;  }
    else if ((j -= N4_X) < N4_WQ) { in = wq; hi = g_wq_hi; }
    else                          { j -= N4_WQ; in = wo; hi = g_wo_hi; }
    float4 v = ((const float4*)in)[j];
    ((uint2*)hi)[j] = make_uint2(pack_h(v.x, v.y), pack_h(v.z, v.w));
}

// ---------------------------------------------------------------------------
// HMMA fp16 GEMM, 1-pass: D = Ah*Bh^T + bias.
// mode 0 (qkv): scatter Q(scaled)/K/V^T fp16;  mode 1: fp32 out.
// BK=32 (SW64). Stage 16KB {Ah@0, Bh@8K} x3 = 48KB. 2 CTAs/SM.
// ---------------------------------------------------------------------------
#define GSTAGE    16384
#define GEMM_SMEM (3*GSTAGE)

__global__ __launch_bounds__(256, 2) void tc_gemm(
    const float* __restrict__ bias, float* __restrict__ out, int mode)
{
    extern __shared__ char sb[];
    const uint32_t sbu = smem_u32(sb);
    const int tid = threadIdx.x;
    const int wid = tid >> 5, lane = tid & 31;
    const int wm = wid >> 2, wn = wid & 3;
    const int m0 = blockIdx.y * 128, n0 = blockIdx.x * 128;

    const char *Ahg, *Bhg;
    if (mode == 0) {
        Ahg = (const char*)(g_x_hi  + (size_t)m0 * EMB);
        Bhg = (const char*)(g_wq_hi + (size_t)n0 * EMB);
    } else {
        Ahg = (const char*)(g_cx_hi + (size_t)m0 * EMB);
        Bhg = (const char*)(g_wo_hi + (size_t)n0 * EMB);
    }

    float acc[4][4][4];
#pragma unroll
    for (int i = 0; i < 4; i++)
#pragma unroll
        for (int j = 0; j < 4; j++)
#pragma unroll
            for (int e = 0; e < 4; e++) acc[i][j][e] = 0.f;

    const int a_r  = (lane & 7) + ((lane >> 3) & 1) * 8;
    const int a_kb = (lane >> 4) * 16;
    const int b_r  = (lane & 7) + (lane >> 4) * 8;
    const int b_kb = ((lane >> 3) & 1) * 16;

    auto load_stage = [&](int c, int s) {
        const uint32_t base = sbu + s * GSTAGE;
#pragma unroll
        for (int it = 0; it < 2; it++) {
            const int idx = tid + it * 256;
            const int r = idx >> 2, cc = (idx & 3) * 16;
            const uint32_t sw = SW64(r * 64 + cc);
            const size_t g = (size_t)r * 2048 + (size_t)c * 64 + cc;
            cp16(base + sw,         Ahg + g);
            cp16(base + 8192 + sw,  Bhg + g);
        }
    };

    load_stage(0, 0); CP_COMMIT();
    load_stage(1, 1); CP_COMMIT();

    for (int c = 0; c < 32; c++) {
        const int buf = c % 3;
        if (c + 2 < 32) { load_stage(c + 2, (c + 2) % 3); CP_COMMIT(); CP_WAIT2(); }
        else if (c == 30) { CP_WAIT1(); }
        else              { CP_WAIT0(); }
        __syncthreads();

        const uint32_t Ah = sbu + buf * GSTAGE;
        const uint32_t Bh = Ah + 8192;
#pragma unroll
        for (int ks = 0; ks < 2; ks++) {
            const int kb = ks * 32;
            uint32_t ah[4][4], bh[2][4];
#pragma unroll
            for (int mt = 0; mt < 4; mt++) {
                const int row = wm * 64 + mt * 16 + a_r;
                ldsm_x4(ah[mt][0], ah[mt][1], ah[mt][2], ah[mt][3],
                        Ah + SW64(row * 64 + kb + a_kb));
            }
#pragma unroll
            for (int p = 0; p < 2; p++) {
                const int row = wn * 32 + p * 16 + b_r;
                ldsm_x4(bh[p][0], bh[p][1], bh[p][2], bh[p][3],
                        Bh + SW64(row * 64 + kb + b_kb));
            }
#pragma unroll
            for (int mt = 0; mt < 4; mt++)
#pragma unroll
                for (int p = 0; p < 2; p++) {
                    mma16816(acc[mt][p*2],   ah[mt][0], ah[mt][1], ah[mt][2], ah[mt][3], bh[p][0], bh[p][1]);
                    mma16816(acc[mt][p*2+1], ah[mt][0], ah[mt][1], ah[mt][2], ah[mt][3], bh[p][2], bh[p][3]);
                }
        }
        __syncthreads();
    }

    const int rbase = m0 + wm * 64 + (lane >> 2);
    const int cbase = n0 + wn * 32 + (lane & 3) * 2;
#pragma unroll
    for (int mt = 0; mt < 4; mt++) {
#pragma unroll
        for (int nt = 0; nt < 4; nt++) {
            const int col = cbase + nt * 8;
            const float bx = bias[col], by = bias[col + 1];
#pragma unroll
            for (int half = 0; half < 2; half++) {
                const int row = rbase + mt * 16 + half * 8;
                float v0 = acc[mt][nt][half * 2 + 0] + bx;
                float v1 = acc[mt][nt][half * 2 + 1] + by;
                if (mode == 1) {
                    *(float2*)(out + (size_t)row * EMB + col) = make_float2(v0, v1);
                } else {
                    const int b = row >> 11, n = row & 2047;
                    const int which = col >> 10;
                    const int hd = col & 1023;
                    const int h = hd >> 6, d = hd & 63;
                    const int bhi = (b << 4) + h;
                    if (which == 0) {
                        const size_t off = ((size_t)bhi * SEQ + n) * HDIM + d;
                        *(uint32_t*)&g_q_hi[off] = pack_h(v0 * QSCALE, v1 * QSCALE);
                    } else if (which == 1) {
                        const size_t off = ((size_t)bhi * SEQ + n) * HDIM + d;
                        *(uint32_t*)&g_k_hi[off] = pack_h(v0, v1);
                    } else {
                        const size_t o0 = ((size_t)bhi * HDIM + d) * SEQ + n;
                        const size_t o1 = ((size_t)bhi * HDIM + d + 1) * SEQ + n;
                        g_vT_hi[o0] = __float2half_rn(v0);
                        g_vT_hi[o1] = __float2half_rn(v1);
                    }
                }
            }
        }
    }
}

// ---------------------------------------------------------------------------
// HMMA flash attention: S = Qh*Kh;  O += Ph*Vh. Register-resident P,
// log2-domain softmax (exp2f). Ctx written fp16.
// Smem: Qh@0(16K) | stage s@16K+s*32K {Kh 16K, VTh 2x8K}. 3 stages. 112KB.
// 2 CTAs/SM.
// ---------------------------------------------------------------------------
#define ASTG      32768
#define AS_KV     16384
#define ATTN_SMEM (AS_KV + 3*ASTG)

__global__ __launch_bounds__(256, 2) void attn_kernel()
{
    extern __shared__ char sb[];
    const uint32_t sbu = smem_u32(sb);
    const int tid = threadIdx.x;
    const int wid = tid >> 5, lane = tid & 31;
    const int bh = blockIdx.x;
    const int q0 = blockIdx.y * 128;

    const int a_r  = (lane & 7) + ((lane >> 3) & 1) * 8;
    const int a_kb = (lane >> 4) * 16;
    const int b_r  = (lane & 7) + (lane >> 4) * 8;
    const int b_kb = ((lane >> 3) & 1) * 16;

    // ---- Q tile ----
    {
        const char* qh = (const char*)(g_q_hi + ((size_t)bh * SEQ + q0) * HDIM);
#pragma unroll
        for (int it = 0; it < 4; it++) {
            const int idx = tid + it * 256;
            const int r = idx >> 3, in = (idx & 7) * 16;
            cp16(sbu + SW(r * 128 + in), qh + r * 128 + in);
        }
    }

    auto load_stage = [&](int kt, int s) {
        const uint32_t base = sbu + AS_KV + s * ASTG;
        const char* kh = (const char*)(g_k_hi + ((size_t)bh * SEQ + kt * 128) * HDIM);
#pragma unroll
        for (int it = 0; it < 4; it++) {
            const int idx = tid + it * 256;
            const int r = idx >> 3, in = (idx & 7) * 16;
            cp16(base + SW(r * 128 + in), kh + r * 128 + in);
        }
        const char* vh = (const char*)(g_vT_hi + (size_t)bh * HDIM * SEQ) + (size_t)kt * 256;
#pragma unroll
        for (int it = 0; it < 4; it++) {
            const int idx = tid + it * 256;
            const int r = idx >> 4;
            const int inner = (idx & 15) * 16;
            const int half = inner >> 7, in128 = inner & 127;
            cp16(base + 16384 + half * 8192 + SW(r * 128 + in128),
                 vh + (size_t)r * 4096 + inner);
        }
    };

    load_stage(0, 0); CP_COMMIT();
    load_stage(1, 1); CP_COMMIT();

    float o[8][4];
    float mi[2], li[2];
#pragma unroll
    for (int i = 0; i < 8; i++)
#pragma unroll
        for (int e = 0; e < 4; e++) o[i][e] = 0.f;
    mi[0] = mi[1] = -1e30f;
    li[0] = li[1] = 0.f;

    const int arow = wid * 16 + a_r;

    for (int kt = 0; kt < 16; kt++) {
        const int buf = kt % 3;
        if (kt + 2 < 16) { load_stage(kt + 2, (kt + 2) % 3); CP_COMMIT(); CP_WAIT2(); }
        else if (kt == 14) { CP_WAIT1(); }
        else               { CP_WAIT0(); }
        __syncthreads();

        const uint32_t Kh = sbu + AS_KV + buf * ASTG;
        const uint32_t Vh = Kh + 16384;

        // ---- S = Qh*Kh ----
        float s[16][4];
#pragma unroll
        for (int i = 0; i < 16; i++)
#pragma unroll
            for (int e = 0; e < 4; e++) s[i][e] = 0.f;

#pragma unroll
        for (int ks = 0; ks < 4; ks++) {
            const int kb = ks * 32;
            uint32_t ah0, ah1, ah2, ah3;
            ldsm_x4(ah0, ah1, ah2, ah3, sbu + SW(arow * 128 + kb + a_kb));
#pragma unroll
            for (int p = 0; p < 8; p++) {
                const int row = p * 16 + b_r;
                uint32_t t0, t1, t2, t3;
                ldsm_x4(t0, t1, t2, t3, Kh + SW(row * 128 + kb + b_kb));
                mma16816(s[p*2],   ah0, ah1, ah2, ah3, t0, t1);
                mma16816(s[p*2+1], ah0, ah1, ah2, ah3, t2, t3);
            }
        }

        // ---- online softmax in log2 domain ----
#pragma unroll
        for (int h = 0; h < 2; h++) {
            float rm = -1e30f;
#pragma unroll
            for (int nt = 0; nt < 16; nt++)
                rm = fmaxf(rm, fmaxf(s[nt][h*2], s[nt][h*2+1]));
            rm = fmaxf(rm, __shfl_xor_sync(0xffffffffu, rm, 1));
            rm = fmaxf(rm, __shfl_xor_sync(0xffffffffu, rm, 2));
            const float m2 = fmaxf(mi[h], rm);
            const float alpha = exp2f(mi[h] - m2);
            float rs = 0.f;
#pragma unroll
            for (int nt = 0; nt < 16; nt++) {
                const float p0 = exp2f(s[nt][h*2]   - m2);
                const float p1 = exp2f(s[nt][h*2+1] - m2);
                s[nt][h*2] = p0; s[nt][h*2+1] = p1;
                rs += p0 + p1;
            }
            rs += __shfl_xor_sync(0xffffffffu, rs, 1);
            rs += __shfl_xor_sync(0xffffffffu, rs, 2);
            li[h] = li[h] * alpha + rs;
            mi[h] = m2;
#pragma unroll
            for (int nt = 0; nt < 8; nt++) {
                o[nt][h*2]   *= alpha;
                o[nt][h*2+1] *= alpha;
            }
        }

        // ---- O += Ph*Vh, P from registers ----
#pragma unroll
        for (int kc = 0; kc < 8; kc++) {
            const int half = kc >> 2;
            const int koff = (kc & 3) * 32;
            const uint32_t ah0 = pack_h(s[2*kc][0],   s[2*kc][1]);
            const uint32_t ah1 = pack_h(s[2*kc][2],   s[2*kc][3]);
            const uint32_t ah2 = pack_h(s[2*kc+1][0], s[2*kc+1][1]);
            const uint32_t ah3 = pack_h(s[2*kc+1][2], s[2*kc+1][3]);
#pragma unroll
            for (int p = 0; p < 4; p++) {
                const int row = p * 16 + b_r;
                uint32_t t0, t1, t2, t3;
                ldsm_x4(t0, t1, t2, t3, Vh + half * 8192 + SW(row * 128 + koff + b_kb));
                mma16816(o[p*2],   ah0, ah1, ah2, ah3, t0, t1);
                mma16816(o[p*2+1], ah0, ah1, ah2, ah3, t2, t3);
            }
        }
        __syncthreads();
    }

    // ---- epilogue: normalize, fp16 ctx in [B,N,H*D] ----
    const int b = bh >> 4, h = bh & 15;
#pragma unroll
    for (int hh = 0; hh < 2; hh++) {
        const float inv = 1.f / li[hh];
        const int row = q0 + wid * 16 + (lane >> 2) + hh * 8;
        const size_t rbase = ((size_t)b * SEQ + row) * EMB + h * HDIM;
#pragma unroll
        for (int nt = 0; nt < 8; nt++) {
            const int col = (lane & 3) * 2 + nt * 8;
            *(uint32_t*)&g_cx_hi[rbase + col] = pack_h(o[nt][hh*2] * inv, o[nt][hh*2+1] * inv);
        }
    }
}

// ---------------------------------------------------------------------------
extern "C" void kernel_launch(void* const* d_in, const int* in_sizes, int n_in,
                              void* d_out, int out_size)
{
    const float* x     = (const float*)d_in[0];
    const float* w_qkv = (const float*)d_in[1];
    const float* b_qkv = (const float*)d_in[2];
    const float* w_out = (const float*)d_in[3];
    const float* b_out = (const float*)d_in[4];
    float* out = (float*)d_out;

    static bool attr_set = false;
    if (!attr_set) {
        cudaFuncSetAttribute(tc_gemm, cudaFuncAttributeMaxDynamicSharedMemorySize, GEMM_SMEM);
        cudaFuncSetAttribute(attn_kernel, cudaFuncAttributeMaxDynamicSharedMemorySize, ATTN_SMEM);
        attr_set = true;
    }

    split_all_kernel<<<(N4_ALL + 255)/256, 256>>>(x, w_qkv, w_out);
    tc_gemm<<<dim3(3*EMB/128, MTOT/128), 256, GEMM_SMEM>>>(b_qkv, nullptr, 0);
    attn_kernel<<<dim3(BH, SEQ/128), 256, ATTN_SMEM>>>();
    tc_gemm<<<dim3(EMB/128, MTOT/128), 256, GEMM_SMEM>>>(b_out, out, 1);
}

// round 17
// speedup vs baseline: 2.3294x; 1.0079x over previous
#include <cuda_runtime.h>
#include <cuda_fp16.h>
#include <cstdint>

#define BATCH   2
#define SEQ     2048
#define EMB     1024
#define HEADS   16
#define HDIM    64
#define MTOT    (BATCH*SEQ)        // 4096
#define BH      (BATCH*HEADS)      // 32
#define QSCALE  (0.125f * 1.4426950408889634f)   // SCALE * log2(e)

// ---------------- scratch (device globals; cudaMalloc forbidden) -----------
__device__ __half g_x_hi[MTOT*EMB];
__device__ __half g_wq_hi[3*EMB*EMB];
__device__ __half g_wo_hi[EMB*EMB];
__device__ __half g_cx_hi[MTOT*EMB];
__device__ __half g_q_hi[BH*SEQ*HDIM];   // [bh][n][d], pre-scaled
__device__ __half g_k_hi[BH*SEQ*HDIM];   // [bh][n][d]
__device__ __half g_vT_hi[BH*HDIM*SEQ];  // [bh][d][n]

// ---------------- helpers --------------------------------------------------
__device__ __forceinline__ uint32_t smem_u32(const void* p) {
    uint32_t a;
    asm("{ .reg .u64 t; cvta.to.shared.u64 t, %1; cvt.u32.u64 %0, t; }"
        : "=r"(a) : "l"(p));
    return a;
}
#define SW(off)   ((uint32_t)(off) ^ ((((uint32_t)(off)) >> 3) & 0x70))   // SW128

__device__ __forceinline__ void ldsm_x4(uint32_t& r0, uint32_t& r1,
                                        uint32_t& r2, uint32_t& r3, uint32_t addr) {
    asm volatile("ldmatrix.sync.aligned.m8n8.x4.shared.b16 {%0,%1,%2,%3}, [%4];"
                 : "=r"(r0), "=r"(r1), "=r"(r2), "=r"(r3) : "r"(addr));
}
__device__ __forceinline__ void mma16816(float c[4],
                                         uint32_t a0, uint32_t a1, uint32_t a2, uint32_t a3,
                                         uint32_t b0, uint32_t b1) {
    asm volatile("mma.sync.aligned.m16n8k16.row.col.f32.f16.f16.f32 "
                 "{%0,%1,%2,%3}, {%4,%5,%6,%7}, {%8,%9}, {%0,%1,%2,%3};"
                 : "+f"(c[0]), "+f"(c[1]), "+f"(c[2]), "+f"(c[3])
                 : "r"(a0), "r"(a1), "r"(a2), "r"(a3), "r"(b0), "r"(b1));
}
__device__ __forceinline__ void cp16(uint32_t dst, const void* src) {
    asm volatile("cp.async.cg.shared.global [%0], [%1], 16;" :: "r"(dst), "l"(src));
}
#define CP_COMMIT()  asm volatile("cp.async.commit_group;" ::: "memory")
#define CP_WAIT0()   asm volatile("cp.async.wait_group 0;" ::: "memory")
#define CP_WAIT1()   asm volatile("cp.async.wait_group 1;" ::: "memory")
#define CP_WAIT2()   asm volatile("cp.async.wait_group 2;" ::: "memory")

__device__ __forceinline__ uint32_t pack_h(float v0, float v1) {
    return (uint32_t)__half_as_ushort(__float2half_rn(v0)) |
           ((uint32_t)__half_as_ushort(__float2half_rn(v1)) << 16);
}

// ---------------------------------------------------------------------------
// Merged convert: x, w_qkv, w_out -> fp16 in ONE launch
// ---------------------------------------------------------------------------
#define N4_X   (MTOT*EMB/4)
#define N4_WQ  (3*EMB*EMB/4)
#define N4_WO  (EMB*EMB/4)
#define N4_ALL (N4_X + N4_WQ + N4_WO)

__global__ __launch_bounds__(256) void split_all_kernel(
    const float* __restrict__ x, const float* __restrict__ wq,
    const float* __restrict__ wo)
{
    int i = blockIdx.x * 256 + threadIdx.x;
    if (i >= N4_ALL) return;
    const float* in;
    __half* hi;
    int j = i;
    if (j < N4_X)                 { in = x;  hi = g_x_hi;  }
    else if ((j -= N4_X) < N4_WQ) { in = wq; hi = g_wq_hi; }
    else                          { j -= N4_WQ; in = wo; hi = g_wo_hi; }
    float4 v = ((const float4*)in)[j];
    ((uint2*)hi)[j] = make_uint2(pack_h(v.x, v.y), pack_h(v.z, v.w));
}

// ---------------------------------------------------------------------------
// HMMA fp16 GEMM, 1-pass, 64x64 warp tiles (crossbar-ratio fix).
// CTA tile 128x256, 8 warps (2x4), BK=64 elems (SW128).
// Stage 48KB {A 16K @0, B 32K @16K} x3 = 144KB, 1 CTA/SM.
// mode 0 (qkv): scatter Q(scaled)/K/V^T fp16;  mode 1: fp32 out.
// ---------------------------------------------------------------------------
#define GSTAGE    49152
#define GEMM_SMEM (3*GSTAGE)

__global__ __launch_bounds__(256, 1) void tc_gemm(
    const float* __restrict__ bias, float* __restrict__ out, int mode)
{
    extern __shared__ char sb[];
    const uint32_t sbu = smem_u32(sb);
    const int tid = threadIdx.x;
    const int wid = tid >> 5, lane = tid & 31;
    const int wm = wid >> 2, wn = wid & 3;            // 2 x 4 warp grid
    const int m0 = blockIdx.y * 128, n0 = blockIdx.x * 256;

    const char *Ahg, *Bhg;
    if (mode == 0) {
        Ahg = (const char*)(g_x_hi  + (size_t)m0 * EMB);
        Bhg = (const char*)(g_wq_hi + (size_t)n0 * EMB);
    } else {
        Ahg = (const char*)(g_cx_hi + (size_t)m0 * EMB);
        Bhg = (const char*)(g_wo_hi + (size_t)n0 * EMB);
    }

    float acc[4][8][4];                // 64 rows x 64 cols per warp
#pragma unroll
    for (int i = 0; i < 4; i++)
#pragma unroll
        for (int j = 0; j < 8; j++)
#pragma unroll
            for (int e = 0; e < 4; e++) acc[i][j][e] = 0.f;

    const int a_r  = (lane & 7) + ((lane >> 3) & 1) * 8;
    const int a_kb = (lane >> 4) * 16;
    const int b_r  = (lane & 7) + (lane >> 4) * 8;
    const int b_kb = ((lane >> 3) & 1) * 16;

    // Stage: A 128 rows x 128B @0; B 256 rows x 128B @16K (both SW128)
    auto load_stage = [&](int c, int s) {
        const uint32_t base = sbu + s * GSTAGE;
#pragma unroll
        for (int it = 0; it < 4; it++) {           // A: 1024 cp16
            const int idx = tid + it * 256;
            const int r = idx >> 3, cc = (idx & 7) * 16;
            cp16(base + SW(r * 128 + cc), Ahg + (size_t)r * 2048 + (size_t)c * 128 + cc);
        }
#pragma unroll
        for (int it = 0; it < 8; it++) {           // B: 2048 cp16
            const int idx = tid + it * 256;
            const int r = idx >> 3, cc = (idx & 7) * 16;
            cp16(base + 16384 + SW(r * 128 + cc), Bhg + (size_t)r * 2048 + (size_t)c * 128 + cc);
        }
    };

    load_stage(0, 0); CP_COMMIT();
    load_stage(1, 1); CP_COMMIT();

    for (int c = 0; c < 16; c++) {
        const int buf = c % 3;
        if (c + 2 < 16) { load_stage(c + 2, (c + 2) % 3); CP_COMMIT(); CP_WAIT2(); }
        else if (c == 14) { CP_WAIT1(); }
        else              { CP_WAIT0(); }
        __syncthreads();

        const uint32_t Ah = sbu + buf * GSTAGE;
        const uint32_t Bh = Ah + 16384;
#pragma unroll
        for (int ks = 0; ks < 4; ks++) {
            const int kb = ks * 32;
            uint32_t ah[4][4], bh[4][4];
#pragma unroll
            for (int mt = 0; mt < 4; mt++) {
                const int row = wm * 64 + mt * 16 + a_r;
                ldsm_x4(ah[mt][0], ah[mt][1], ah[mt][2], ah[mt][3],
                        Ah + SW(row * 128 + kb + a_kb));
            }
#pragma unroll
            for (int p = 0; p < 4; p++) {
                const int row = wn * 64 + p * 16 + b_r;
                ldsm_x4(bh[p][0], bh[p][1], bh[p][2], bh[p][3],
                        Bh + SW(row * 128 + kb + b_kb));
            }
#pragma unroll
            for (int mt = 0; mt < 4; mt++)
#pragma unroll
                for (int p = 0; p < 4; p++) {
                    mma16816(acc[mt][p*2],   ah[mt][0], ah[mt][1], ah[mt][2], ah[mt][3], bh[p][0], bh[p][1]);
                    mma16816(acc[mt][p*2+1], ah[mt][0], ah[mt][1], ah[mt][2], ah[mt][3], bh[p][2], bh[p][3]);
                }
        }
        __syncthreads();
    }

    const int rbase = m0 + wm * 64 + (lane >> 2);
    const int cbase = n0 + wn * 64 + (lane & 3) * 2;
#pragma unroll
    for (int mt = 0; mt < 4; mt++) {
#pragma unroll
        for (int nt = 0; nt < 8; nt++) {
            const int col = cbase + nt * 8;
            const float bx = bias[col], by = bias[col + 1];
#pragma unroll
            for (int half = 0; half < 2; half++) {
                const int row = rbase + mt * 16 + half * 8;
                float v0 = acc[mt][nt][half * 2 + 0] + bx;
                float v1 = acc[mt][nt][half * 2 + 1] + by;
                if (mode == 1) {
                    *(float2*)(out + (size_t)row * EMB + col) = make_float2(v0, v1);
                } else {
                    const int b = row >> 11, n = row & 2047;
                    const int which = col >> 10;
                    const int hd = col & 1023;
                    const int h = hd >> 6, d = hd & 63;
                    const int bhi = (b << 4) + h;
                    if (which == 0) {
                        const size_t off = ((size_t)bhi * SEQ + n) * HDIM + d;
                        *(uint32_t*)&g_q_hi[off] = pack_h(v0 * QSCALE, v1 * QSCALE);
                    } else if (which == 1) {
                        const size_t off = ((size_t)bhi * SEQ + n) * HDIM + d;
                        *(uint32_t*)&g_k_hi[off] = pack_h(v0, v1);
                    } else {
                        const size_t o0 = ((size_t)bhi * HDIM + d) * SEQ + n;
                        const size_t o1 = ((size_t)bhi * HDIM + d + 1) * SEQ + n;
                        g_vT_hi[o0] = __float2half_rn(v0);
                        g_vT_hi[o1] = __float2half_rn(v1);
                    }
                }
            }
        }
    }
}

// ---------------------------------------------------------------------------
// HMMA flash attention (unchanged from R16): S = Qh*Kh;  O += Ph*Vh.
// Register-resident P, log2-domain softmax. 112KB smem, 2 CTAs/SM.
// ---------------------------------------------------------------------------
#define ASTG      32768
#define AS_KV     16384
#define ATTN_SMEM (AS_KV + 3*ASTG)

__global__ __launch_bounds__(256, 2) void attn_kernel()
{
    extern __shared__ char sb[];
    const uint32_t sbu = smem_u32(sb);
    const int tid = threadIdx.x;
    const int wid = tid >> 5, lane = tid & 31;
    const int bh = blockIdx.x;
    const int q0 = blockIdx.y * 128;

    const int a_r  = (lane & 7) + ((lane >> 3) & 1) * 8;
    const int a_kb = (lane >> 4) * 16;
    const int b_r  = (lane & 7) + (lane >> 4) * 8;
    const int b_kb = ((lane >> 3) & 1) * 16;

    {
        const char* qh = (const char*)(g_q_hi + ((size_t)bh * SEQ + q0) * HDIM);
#pragma unroll
        for (int it = 0; it < 4; it++) {
            const int idx = tid + it * 256;
            const int r = idx >> 3, in = (idx & 7) * 16;
            cp16(sbu + SW(r * 128 + in), qh + r * 128 + in);
        }
    }

    auto load_stage = [&](int kt, int s) {
        const uint32_t base = sbu + AS_KV + s * ASTG;
        const char* kh = (const char*)(g_k_hi + ((size_t)bh * SEQ + kt * 128) * HDIM);
#pragma unroll
        for (int it = 0; it < 4; it++) {
            const int idx = tid + it * 256;
            const int r = idx >> 3, in = (idx & 7) * 16;
            cp16(base + SW(r * 128 + in), kh + r * 128 + in);
        }
        const char* vh = (const char*)(g_vT_hi + (size_t)bh * HDIM * SEQ) + (size_t)kt * 256;
#pragma unroll
        for (int it = 0; it < 4; it++) {
            const int idx = tid + it * 256;
            const int r = idx >> 4;
            const int inner = (idx & 15) * 16;
            const int half = inner >> 7, in128 = inner & 127;
            cp16(base + 16384 + half * 8192 + SW(r * 128 + in128),
                 vh + (size_t)r * 4096 + inner);
        }
    };

    load_stage(0, 0); CP_COMMIT();
    load_stage(1, 1); CP_COMMIT();

    float o[8][4];
    float mi[2], li[2];
#pragma unroll
    for (int i = 0; i < 8; i++)
#pragma unroll
        for (int e = 0; e < 4; e++) o[i][e] = 0.f;
    mi[0] = mi[1] = -1e30f;
    li[0] = li[1] = 0.f;

    const int arow = wid * 16 + a_r;

    for (int kt = 0; kt < 16; kt++) {
        const int buf = kt % 3;
        if (kt + 2 < 16) { load_stage(kt + 2, (kt + 2) % 3); CP_COMMIT(); CP_WAIT2(); }
        else if (kt == 14) { CP_WAIT1(); }
        else               { CP_WAIT0(); }
        __syncthreads();

        const uint32_t Kh = sbu + AS_KV + buf * ASTG;
        const uint32_t Vh = Kh + 16384;

        float s[16][4];
#pragma unroll
        for (int i = 0; i < 16; i++)
#pragma unroll
            for (int e = 0; e < 4; e++) s[i][e] = 0.f;

#pragma unroll
        for (int ks = 0; ks < 4; ks++) {
            const int kb = ks * 32;
            uint32_t ah0, ah1, ah2, ah3;
            ldsm_x4(ah0, ah1, ah2, ah3, sbu + SW(arow * 128 + kb + a_kb));
#pragma unroll
            for (int p = 0; p < 8; p++) {
                const int row = p * 16 + b_r;
                uint32_t t0, t1, t2, t3;
                ldsm_x4(t0, t1, t2, t3, Kh + SW(row * 128 + kb + b_kb));
                mma16816(s[p*2],   ah0, ah1, ah2, ah3, t0, t1);
                mma16816(s[p*2+1], ah0, ah1, ah2, ah3, t2, t3);
            }
        }

#pragma unroll
        for (int h = 0; h < 2; h++) {
            float rm = -1e30f;
#pragma unroll
            for (int nt = 0; nt < 16; nt++)
                rm = fmaxf(rm, fmaxf(s[nt][h*2], s[nt][h*2+1]));
            rm = fmaxf(rm, __shfl_xor_sync(0xffffffffu, rm, 1));
            rm = fmaxf(rm, __shfl_xor_sync(0xffffffffu, rm, 2));
            const float m2 = fmaxf(mi[h], rm);
            const float alpha = exp2f(mi[h] - m2);
            float rs = 0.f;
#pragma unroll
            for (int nt = 0; nt < 16; nt++) {
                const float p0 = exp2f(s[nt][h*2]   - m2);
                const float p1 = exp2f(s[nt][h*2+1] - m2);
                s[nt][h*2] = p0; s[nt][h*2+1] = p1;
                rs += p0 + p1;
            }
            rs += __shfl_xor_sync(0xffffffffu, rs, 1);
            rs += __shfl_xor_sync(0xffffffffu, rs, 2);
            li[h] = li[h] * alpha + rs;
            mi[h] = m2;
#pragma unroll
            for (int nt = 0; nt < 8; nt++) {
                o[nt][h*2]   *= alpha;
                o[nt][h*2+1] *= alpha;
            }
        }

#pragma unroll
        for (int kc = 0; kc < 8; kc++) {
            const int half = kc >> 2;
            const int koff = (kc & 3) * 32;
            const uint32_t ah0 = pack_h(s[2*kc][0],   s[2*kc][1]);
            const uint32_t ah1 = pack_h(s[2*kc][2],   s[2*kc][3]);
            const uint32_t ah2 = pack_h(s[2*kc+1][0], s[2*kc+1][1]);
            const uint32_t ah3 = pack_h(s[2*kc+1][2], s[2*kc+1][3]);
#pragma unroll
            for (int p = 0; p < 4; p++) {
                const int row = p * 16 + b_r;
                uint32_t t0, t1, t2, t3;
                ldsm_x4(t0, t1, t2, t3, Vh + half * 8192 + SW(row * 128 + koff + b_kb));
                mma16816(o[p*2],   ah0, ah1, ah2, ah3, t0, t1);
                mma16816(o[p*2+1], ah0, ah1, ah2, ah3, t2, t3);
            }
        }
        __syncthreads();
    }

    const int b = bh >> 4, h = bh & 15;
#pragma unroll
    for (int hh = 0; hh < 2; hh++) {
        const float inv = 1.f / li[hh];
        const int row = q0 + wid * 16 + (lane >> 2) + hh * 8;
        const size_t rbase = ((size_t)b * SEQ + row) * EMB + h * HDIM;
#pragma unroll
        for (int nt = 0; nt < 8; nt++) {
            const int col = (lane & 3) * 2 + nt * 8;
            *(uint32_t*)&g_cx_hi[rbase + col] = pack_h(o[nt][hh*2] * inv, o[nt][hh*2+1] * inv);
        }
    }
}

// ---------------------------------------------------------------------------
extern "C" void kernel_launch(void* const* d_in, const int* in_sizes, int n_in,
                              void* d_out, int out_size)
{
    const float* x     = (const float*)d_in[0];
    const float* w_qkv = (const float*)d_in[1];
    const float* b_qkv = (const float*)d_in[2];
    const float* w_out = (const float*)d_in[3];
    const float* b_out = (const float*)d_in[4];
    float* out = (float*)d_out;

    static bool attr_set = false;
    if (!attr_set) {
        cudaFuncSetAttribute(tc_gemm, cudaFuncAttributeMaxDynamicSharedMemorySize, GEMM_SMEM);
        cudaFuncSetAttribute(attn_kernel, cudaFuncAttributeMaxDynamicSharedMemorySize, ATTN_SMEM);
        attr_set = true;
    }

    split_all_kernel<<<(N4_ALL + 255)/256, 256>>>(x, w_qkv, w_out);
    tc_gemm<<<dim3(3*EMB/256, MTOT/128), 256, GEMM_SMEM>>>(b_qkv, nullptr, 0);
    attn_kernel<<<dim3(BH, SEQ/128), 256, ATTN_SMEM>>>();
    tc_gemm<<<dim3(EMB/256, MTOT/128), 256, GEMM_SMEM>>>(b_out, out, 1);
}